// round 4
// baseline (speedup 1.0000x reference)
#include <cuda_runtime.h>
#include <cuda_bf16.h>
#include <math.h>
#include <cstdint>

#define HW     16384
#define IMG_H  128
#define IMG_W  128
#define BSZ    4
#define CIN    720
#define MID    512
#define NCLS   19
#define KCH    256
#define VCH    256

#define PH 130
#define PW 130

// conv tiling: CTA 128(m) x 256(n), K-chunk 48, 8 warps (2m x 4n), warp tile 64x64
#define KCH_C     48
#define NCHUNKS   135         // 9 shifts * 15 chunks
#define ASTR      56          // padded row length (bf16) -> 112B stride, conflict-free
#define REG_A     (128*ASTR)
#define REG_B     (256*ASTR)
#define OFFB_AH   0
#define OFFB_AL   (REG_A*2)
#define OFFB_BH   (2*REG_A*2)
#define OFFB_BL   ((2*REG_A + REG_B)*2)
#define STAGE_BYTES ((2*REG_A + 2*REG_B)*2)   // 86016
#define SMEM_DYN  (2*STAGE_BYTES)             // 172032

// ---------------- scratch ----------------
__device__ float g_x    [BSZ*MID*HW];
__device__ float g_qwT  [MID*KCH];
__device__ float g_owT  [VCH*MID];
__device__ float g_probs[BSZ*NCLS*HW];
__device__ float g_S    [BSZ*NCLS];
__device__ float g_ctx  [BSZ*NCLS*MID];
__device__ float g_kmat [BSZ*NCLS*KCH];
__device__ float g_vmat [BSZ*NCLS*VCH];
__device__ float g_q    [BSZ*HW*KCH];
__device__ float g_agg  [BSZ*VCH*HW];
__device__ float g_scale[MID];
__device__ float g_shift[MID];
__device__ __align__(16) __nv_bfloat16 g_fhi[BSZ*PH*PW*CIN];
__device__ __align__(16) __nv_bfloat16 g_flo[BSZ*PH*PW*CIN];
__device__ __align__(16) __nv_bfloat16 g_whi[9*MID*CIN];
__device__ __align__(16) __nv_bfloat16 g_wlo[9*MID*CIN];

// ---------------- helpers ----------------
__device__ __forceinline__ uint32_t smem_u32(const void* p) {
    uint32_t a;
    asm("{ .reg .u64 t; cvta.to.shared.u64 t, %1; cvt.u32.u64 %0, t; }" : "=r"(a) : "l"(p));
    return a;
}
__device__ __forceinline__ void cp16(uint32_t s, const void* g) {
    asm volatile("cp.async.cg.shared.global [%0], [%1], 16;" :: "r"(s), "l"(g));
}
__device__ __forceinline__ void cp_commit() {
    asm volatile("cp.async.commit_group;");
}
__device__ __forceinline__ void mma16816(float* d, const uint32_t* a, const uint32_t* b) {
    asm volatile(
        "mma.sync.aligned.m16n8k16.row.col.f32.bf16.bf16.f32 "
        "{%0,%1,%2,%3}, {%4,%5,%6,%7}, {%8,%9}, {%0,%1,%2,%3};"
        : "+f"(d[0]), "+f"(d[1]), "+f"(d[2]), "+f"(d[3])
        : "r"(a[0]), "r"(a[1]), "r"(a[2]), "r"(a[3]), "r"(b[0]), "r"(b[1]));
}
#define LDSM4(r0, r1, r2, r3, addr) \
    asm volatile("ldmatrix.sync.aligned.m8n8.x4.shared.b16 {%0,%1,%2,%3}, [%4];" \
        : "=r"(r0), "=r"(r1), "=r"(r2), "=r"(r3) : "r"(addr))

// ---------------- prep: zero padded bf16 buffers ----------------
__global__ void zero_pad() {
    long i = (long)blockIdx.x * 256 + threadIdx.x;
    const long n4 = (long)BSZ*PH*PW*CIN / 8;
    if (i < n4)        ((float4*)g_fhi)[i] = make_float4(0.f, 0.f, 0.f, 0.f);
    else if (i < 2*n4) ((float4*)g_flo)[i - n4] = make_float4(0.f, 0.f, 0.f, 0.f);
}

// ---------------- prep: NHWC bf16 hi/lo of feats (padded) ----------------
__global__ __launch_bounds__(256) void nhwc_prep(const float* __restrict__ feats) {
    __shared__ float tile[64][129];
    int by = blockIdx.x;
    int b = by >> 7, h = by & 127;
    int tid = threadIdx.x;
    const float* fb = feats + ((long)b * CIN) * HW + h * IMG_W;
    long obase = ((long)(b * PH + h + 1) * PW + 1) * CIN;
    for (int c0 = 0; c0 < CIN; c0 += 64) {
        int cw = CIN - c0; if (cw > 64) cw = 64;
        #pragma unroll 4
        for (int j = 0; j < 32; j++) {
            int idx = tid + j * 256;
            int c = idx >> 7, w = idx & 127;
            if (c < cw) tile[c][w] = fb[(long)(c0 + c) * HW + w];
        }
        __syncthreads();
        #pragma unroll 4
        for (int j = 0; j < 32; j++) {
            int idx = tid + j * 256;
            int w = idx >> 6, c = idx & 63;
            if (c < cw) {
                float v = tile[c][w];
                __nv_bfloat16 hi = __float2bfloat16(v);
                __nv_bfloat16 lo = __float2bfloat16(v - __bfloat162float(hi));
                long o = obase + (long)w * CIN + c0 + c;
                g_fhi[o] = hi;
                g_flo[o] = lo;
            }
        }
        __syncthreads();
    }
}

// ---------------- prep: weights [r][o][c] bf16 hi/lo ----------------
__global__ void w3_prep(const float* __restrict__ w3) {
    int e = blockIdx.x * 256 + threadIdx.x;
    if (e >= 9 * MID * CIN) return;
    int r = e / (MID * CIN);
    int rem = e - r * (MID * CIN);
    int o = rem / CIN;
    int c = rem - o * CIN;
    float v = w3[(o * CIN + c) * 9 + r];
    __nv_bfloat16 hi = __float2bfloat16(v);
    g_whi[e] = hi;
    g_wlo[e] = __float2bfloat16(v - __bfloat162float(hi));
}

// ---------------- zero small accumulators ----------------
__global__ void zero_kernel() {
    int i = blockIdx.x * 256 + threadIdx.x;
    if (i < BSZ*NCLS*MID) g_ctx[i] = 0.f;
    if (i < BSZ*NCLS)     g_S[i]   = 0.f;
}

// ---------------- transpose small weights ----------------
__global__ void prep_transpose(const float* __restrict__ qw, const float* __restrict__ ow) {
    int i = blockIdx.x * 256 + threadIdx.x;
    if (i < KCH*MID) {
        int d = i / MID; int c = i - d*MID;
        g_qwT[c*KCH + d] = qw[i];
    }
    if (i < MID*VCH) {
        int c = i / VCH; int v = i - c*VCH;
        g_owT[v*MID + c] = ow[i];
    }
}

// ---------------- conv3x3 via mma.sync bf16x3 + ldmatrix ----------------
// grid (2, 512): x = 256-col channel block, y = (b,h). 256 threads = 8 warps (2m x 4n).
__global__ void __launch_bounds__(256, 1) conv_mma() {
    extern __shared__ __nv_bfloat16 sm[];
    uint32_t sbase = smem_u32(sm);
    int tid = threadIdx.x;
    int lane = tid & 31, warp = tid >> 5;
    int wm = warp & 1, wn = warp >> 1;
    int bn = blockIdx.x * 256;
    int by = blockIdx.y;
    int b = by >> 7, h = by & 127;

    const __nv_bfloat16* fhi_b = g_fhi + (long)b * PH * PW * CIN;
    const __nv_bfloat16* flo_b = g_flo + (long)b * PH * PW * CIN;

    // ldmatrix per-lane byte offsets within a region
    uint32_t a_loff = (uint32_t)((lane & 15) * 112 + (lane >> 4) * 16);
    uint32_t b_loff = (uint32_t)(((lane & 7) + ((lane >> 4) & 1) * 8) * 112 + ((lane >> 3) & 1) * 16);

    float d[4][8][4];
    #pragma unroll
    for (int mt = 0; mt < 4; mt++)
        #pragma unroll
        for (int nt = 0; nt < 8; nt++)
            #pragma unroll
            for (int e = 0; e < 4; e++) d[mt][nt][e] = 0.f;

    // prefetch walker
    int nr = 0, nci = 0, nc0 = 0;

    // prologue: chunk 0 -> stage 0
    {
        uint32_t st = sbase;
        long abase = ((long)h * PW + 0) * CIN;       // ky=0, kx=0
        #pragma unroll
        for (int j = 0; j < 4; j++) {
            int idx = tid + j * 256;
            int row = idx >> 3, slot = idx & 7;
            if (slot < 6) {
                uint32_t so = (uint32_t)(row * 112 + slot * 16);
                long go = abase + (long)row * CIN + slot * 8;
                cp16(st + OFFB_AH + so, fhi_b + go);
                cp16(st + OFFB_AL + so, flo_b + go);
            }
        }
        long bbase = (long)bn * CIN;                  // r=0
        #pragma unroll
        for (int j = 0; j < 8; j++) {
            int idx = tid + j * 256;
            int row = idx >> 3, slot = idx & 7;
            if (slot < 6) {
                uint32_t so = (uint32_t)(row * 112 + slot * 16);
                long go = bbase + (long)row * CIN + slot * 8;
                cp16(st + OFFB_BH + so, g_whi + go);
                cp16(st + OFFB_BL + so, g_wlo + go);
            }
        }
        cp_commit();
    }
    nci = 1; nc0 = KCH_C;

    for (int it = 0; it < NCHUNKS; it++) {
        int s = it & 1;
        if (it + 1 < NCHUNKS) {
            uint32_t st = sbase + (uint32_t)(1 - s) * STAGE_BYTES;
            int ky = nr / 3, kx = nr - ky * 3;
            long abase = ((long)(h + ky) * PW + kx) * CIN + nc0;
            #pragma unroll
            for (int j = 0; j < 4; j++) {
                int idx = tid + j * 256;
                int row = idx >> 3, slot = idx & 7;
                if (slot < 6) {
                    uint32_t so = (uint32_t)(row * 112 + slot * 16);
                    long go = abase + (long)row * CIN + slot * 8;
                    cp16(st + OFFB_AH + so, fhi_b + go);
                    cp16(st + OFFB_AL + so, flo_b + go);
                }
            }
            long bbase = ((long)nr * MID + bn) * CIN + nc0;
            #pragma unroll
            for (int j = 0; j < 8; j++) {
                int idx = tid + j * 256;
                int row = idx >> 3, slot = idx & 7;
                if (slot < 6) {
                    uint32_t so = (uint32_t)(row * 112 + slot * 16);
                    long go = bbase + (long)row * CIN + slot * 8;
                    cp16(st + OFFB_BH + so, g_whi + go);
                    cp16(st + OFFB_BL + so, g_wlo + go);
                }
            }
            cp_commit();
            nci++; nc0 += KCH_C;
            if (nci == 15) { nci = 0; nc0 = 0; nr++; }
            asm volatile("cp.async.wait_group 1;");
        } else {
            asm volatile("cp.async.wait_group 0;");
        }
        __syncthreads();

        uint32_t st = sbase + (uint32_t)s * STAGE_BYTES;
        #pragma unroll
        for (int ks = 0; ks < 3; ks++) {
            uint32_t kb = (uint32_t)ks * 32;   // 16 bf16 = 32 bytes
            uint32_t bh[8][2], bl[8][2];
            #pragma unroll
            for (int g = 0; g < 4; g++) {
                uint32_t nb = (uint32_t)(wn * 64 + g * 16) * 112;
                LDSM4(bh[2*g][0], bh[2*g][1], bh[2*g+1][0], bh[2*g+1][1],
                      st + OFFB_BH + nb + kb + b_loff);
                LDSM4(bl[2*g][0], bl[2*g][1], bl[2*g+1][0], bl[2*g+1][1],
                      st + OFFB_BL + nb + kb + b_loff);
            }
            #pragma unroll
            for (int mt = 0; mt < 4; mt++) {
                uint32_t mb = (uint32_t)(wm * 64 + mt * 16) * 112;
                uint32_t ah[4], al[4];
                LDSM4(ah[0], ah[1], ah[2], ah[3], st + OFFB_AH + mb + kb + a_loff);
                LDSM4(al[0], al[1], al[2], al[3], st + OFFB_AL + mb + kb + a_loff);
                #pragma unroll
                for (int nt = 0; nt < 8; nt++) {
                    mma16816(d[mt][nt], ah, bh[nt]);
                    mma16816(d[mt][nt], ah, bl[nt]);
                    mma16816(d[mt][nt], al, bh[nt]);
                }
            }
        }
        __syncthreads();
    }

    // epilogue: direct fragment stores (full 32B sectors per 8-lane row group)
    int qrow = lane >> 2, qcol = (lane & 3) * 2;
    int pixm = h * IMG_W + wm * 64 + qrow;
    #pragma unroll
    for (int mt = 0; mt < 4; mt++) {
        #pragma unroll
        for (int nt = 0; nt < 8; nt++) {
            long n = bn + wn * 64 + nt * 8 + qcol;
            float* p0 = g_x + ((long)b * MID + n) * HW + pixm + mt * 16;
            p0[0]           = d[mt][nt][0];
            p0[HW]          = d[mt][nt][1];
            p0[8]           = d[mt][nt][2];
            p0[HW + 8]      = d[mt][nt][3];
        }
    }
}

// ---------------- BN stats per channel ----------------
__global__ void bn_stats(const float* __restrict__ gamma, const float* __restrict__ beta) {
    int c = blockIdx.x, tid = threadIdx.x;
    float s = 0.f, sq = 0.f;
    for (int b = 0; b < BSZ; b++) {
        const float* p = g_x + (b*MID + c)*HW;
        for (int i = tid; i < HW; i += 256) { float v = p[i]; s += v; sq += v*v; }
    }
    __shared__ float ss[256], s2[256];
    ss[tid] = s; s2[tid] = sq; __syncthreads();
    for (int st = 128; st > 0; st >>= 1) {
        if (tid < st) { ss[tid] += ss[tid+st]; s2[tid] += s2[tid+st]; }
        __syncthreads();
    }
    if (tid == 0) {
        float n    = (float)(BSZ*HW);
        float mean = ss[0] / n;
        float var  = s2[0] / n - mean*mean;
        float rstd = rsqrtf(var + 1e-5f);
        float sc   = gamma[c] * rstd;
        g_scale[c] = sc;
        g_shift[c] = beta[c] - mean * sc;
    }
}

// ---------------- fused: BN apply + relu + aux head + softmax + prob sums ----------------
__global__ __launch_bounds__(256)
void bn_aux_softmax(const float* __restrict__ aux_w, const float* __restrict__ aux_b,
                    float* __restrict__ aux_out) {
    __shared__ float sw[NCLS*MID];
    __shared__ float ssc[MID], ssh[MID];
    __shared__ float sb[NCLS], sS[NCLS];
    int tid = threadIdx.x;
    for (int i = tid; i < NCLS*MID; i += 256) sw[i] = aux_w[i];
    for (int i = tid; i < MID; i += 256) { ssc[i] = g_scale[i]; ssh[i] = g_shift[i]; }
    if (tid < NCLS) { sb[tid] = aux_b[tid]; sS[tid] = 0.f; }
    __syncthreads();

    int pix = blockIdx.x * 256 + tid;
    int b   = pix >> 14;
    int hw  = pix & (HW-1);
    float acc[NCLS];
    #pragma unroll
    for (int k = 0; k < NCLS; k++) acc[k] = 0.f;

    float* xb = g_x + (b*MID)*HW + hw;
    for (int c = 0; c < MID; c++) {
        float v = xb[c*HW];
        v = fmaf(v, ssc[c], ssh[c]);
        v = fmaxf(v, 0.f);
        xb[c*HW] = v;
        #pragma unroll
        for (int k = 0; k < NCLS; k++) acc[k] = fmaf(v, sw[k*MID + c], acc[k]);
    }
    float mx = -1e30f;
    #pragma unroll
    for (int k = 0; k < NCLS; k++) {
        acc[k] += sb[k];
        aux_out[(b*NCLS + k)*HW + hw] = acc[k];
        mx = fmaxf(mx, acc[k]);
    }
    float sum = 0.f;
    #pragma unroll
    for (int k = 0; k < NCLS; k++) { acc[k] = expf(acc[k] - mx); sum += acc[k]; }
    float inv = 1.f / sum;
    #pragma unroll
    for (int k = 0; k < NCLS; k++) {
        float p = acc[k] * inv;
        g_probs[(b*NCLS + k)*HW + hw] = p;
        atomicAdd(&sS[k], p);
    }
    __syncthreads();
    if (tid < NCLS) atomicAdd(&g_S[b*NCLS + tid], sS[tid]);
}

// ---------------- context ----------------
__global__ __launch_bounds__(512)
void context_kernel() {
    __shared__ float pw[NCLS][512];
    int b   = blockIdx.y;
    int n0  = blockIdx.x * 512;
    int tid = threadIdx.x;
    for (int k = 0; k < NCLS; k++)
        pw[k][tid] = g_probs[(b*NCLS + k)*HW + n0 + tid];
    __syncthreads();

    float acc[NCLS];
    #pragma unroll
    for (int k = 0; k < NCLS; k++) acc[k] = 0.f;
    const float* xr = g_x + (b*MID + tid)*HW + n0;
    for (int n = 0; n < 512; n += 4) {
        float4 xv = *(const float4*)(xr + n);
        float vv[4] = {xv.x, xv.y, xv.z, xv.w};
        #pragma unroll
        for (int dn = 0; dn < 4; dn++) {
            float v = vv[dn];
            #pragma unroll
            for (int k = 0; k < NCLS; k++) acc[k] = fmaf(v, pw[k][n + dn], acc[k]);
        }
    }
    #pragma unroll
    for (int k = 0; k < NCLS; k++)
        atomicAdd(&g_ctx[(b*NCLS + k)*MID + tid], acc[k]);
}

// ---------------- k,v from normalized context ----------------
__global__ __launch_bounds__(256)
void kv_kernel(const float* __restrict__ k_w, const float* __restrict__ k_b,
               const float* __restrict__ v_w, const float* __restrict__ v_b) {
    int b  = blockIdx.x / NCLS;
    int kc = blockIdx.x % NCLS;
    __shared__ float ctx[MID];
    int tid = threadIdx.x;
    float S = fmaxf(g_S[b*NCLS + kc], 1e-6f);
    float invS = 1.f / S;
    for (int i = tid; i < MID; i += 256)
        ctx[i] = g_ctx[(b*NCLS + kc)*MID + i] * invS;
    __syncthreads();

    float kk = k_b[tid], vv = v_b[tid];
    const float4* kw4 = (const float4*)(k_w + tid*MID);
    const float4* vw4 = (const float4*)(v_w + tid*MID);
    for (int c4 = 0; c4 < MID/4; c4++) {
        float4 kw = kw4[c4], vw = vw4[c4];
        float c0 = ctx[c4*4], c1 = ctx[c4*4+1], c2 = ctx[c4*4+2], c3 = ctx[c4*4+3];
        kk = fmaf(c0, kw.x, fmaf(c1, kw.y, fmaf(c2, kw.z, fmaf(c3, kw.w, kk))));
        vv = fmaf(c0, vw.x, fmaf(c1, vw.y, fmaf(c2, vw.z, fmaf(c3, vw.w, vv))));
    }
    g_kmat[(b*NCLS + kc)*KCH + tid] = kk;
    g_vmat[(b*NCLS + kc)*VCH + tid] = vv;
}

// ---------------- q = x * q_w^T ----------------
__global__ __launch_bounds__(256)
void gemm_q() {
    __shared__ float As[8][128];
    __shared__ float Bs[8][128];
    int tid = threadIdx.x;
    int bn = blockIdx.x * 128;
    int by = blockIdx.y;
    int b = by >> 7, h = by & 127;

    int la_m = tid & 127, la_k = tid >> 7;
    int lb_n = tid & 127, lb_k = tid >> 7;
    float acc[8][8];
    #pragma unroll
    for (int i = 0; i < 8; i++)
        #pragma unroll
        for (int j = 0; j < 8; j++) acc[i][j] = 0.f;
    int tx = tid & 15, ty = tid >> 4;

    const float* Ab = g_x + (b*MID)*HW + h*IMG_W;
    for (int k0 = 0; k0 < MID; k0 += 8) {
        #pragma unroll
        for (int i = 0; i < 4; i++) {
            int kk = la_k + 2*i;
            As[kk][la_m] = Ab[(k0 + kk)*HW + la_m];
        }
        #pragma unroll
        for (int i = 0; i < 4; i++) {
            int kk = lb_k + 2*i;
            Bs[kk][lb_n] = g_qwT[(k0 + kk)*KCH + bn + lb_n];
        }
        __syncthreads();
        #pragma unroll
        for (int kk = 0; kk < 8; kk++) {
            float4 a0 = *(const float4*)&As[kk][ty*8];
            float4 a1 = *(const float4*)&As[kk][ty*8+4];
            float4 b0 = *(const float4*)&Bs[kk][tx*8];
            float4 b1 = *(const float4*)&Bs[kk][tx*8+4];
            float ar[8] = {a0.x,a0.y,a0.z,a0.w,a1.x,a1.y,a1.z,a1.w};
            float br[8] = {b0.x,b0.y,b0.z,b0.w,b1.x,b1.y,b1.z,b1.w};
            #pragma unroll
            for (int i = 0; i < 8; i++)
                #pragma unroll
                for (int j = 0; j < 8; j++)
                    acc[i][j] = fmaf(ar[i], br[j], acc[i][j]);
        }
        __syncthreads();
    }
    int m0 = (b << 14) + h*IMG_W;
    #pragma unroll
    for (int i = 0; i < 8; i++) {
        int m = m0 + ty*8 + i;
        float4 v0 = make_float4(acc[i][0], acc[i][1], acc[i][2], acc[i][3]);
        float4 v1 = make_float4(acc[i][4], acc[i][5], acc[i][6], acc[i][7]);
        *(float4*)(g_q + m*KCH + bn + tx*8)     = v0;
        *(float4*)(g_q + m*KCH + bn + tx*8 + 4) = v1;
    }
}

// ---------------- attention ----------------
__global__ __launch_bounds__(256)
void attention_kernel() {
    __shared__ float ks[NCLS*KCH];
    __shared__ float vs[NCLS*VCH];
    int tid = threadIdx.x;
    int pix = blockIdx.x * 256 + tid;
    int b = pix >> 14, hw = pix & (HW-1);
    for (int i = tid; i < NCLS*KCH; i += 256) ks[i] = g_kmat[b*NCLS*KCH + i];
    for (int i = tid; i < NCLS*VCH; i += 256) vs[i] = g_vmat[b*NCLS*VCH + i];
    __syncthreads();

    float s[NCLS];
    #pragma unroll
    for (int k = 0; k < NCLS; k++) s[k] = 0.f;
    const float4* qp = (const float4*)(g_q + (long)pix*KCH);
    for (int d4 = 0; d4 < KCH/4; d4++) {
        float4 q4 = qp[d4];
        float qv[4] = {q4.x, q4.y, q4.z, q4.w};
        #pragma unroll
        for (int j = 0; j < 4; j++) {
            float q = qv[j];
            int d = d4*4 + j;
            #pragma unroll
            for (int k = 0; k < NCLS; k++) s[k] = fmaf(q, ks[k*KCH + d], s[k]);
        }
    }
    const float scale = 0.0625f;
    float mx = -1e30f;
    #pragma unroll
    for (int k = 0; k < NCLS; k++) { s[k] *= scale; mx = fmaxf(mx, s[k]); }
    float sum = 0.f;
    #pragma unroll
    for (int k = 0; k < NCLS; k++) { s[k] = expf(s[k] - mx); sum += s[k]; }
    float inv = 1.f / sum;
    #pragma unroll
    for (int k = 0; k < NCLS; k++) s[k] *= inv;

    for (int v = 0; v < VCH; v++) {
        float o = 0.f;
        #pragma unroll
        for (int k = 0; k < NCLS; k++) o = fmaf(s[k], vs[k*VCH + v], o);
        g_agg[(b*VCH + v)*HW + hw] = o;
    }
}

// ---------------- obj = agg * out_w^T, x += obj ----------------
__global__ __launch_bounds__(256)
void gemm_obj() {
    __shared__ float As[8][128];
    __shared__ float Bs[8][128];
    int tid = threadIdx.x;
    int bn = blockIdx.x * 128;
    int by = blockIdx.y;
    int b = by >> 7, h = by & 127;

    int la_m = tid & 127, la_k = tid >> 7;
    int lb_n = tid & 127, lb_k = tid >> 7;
    float acc[8][8];
    #pragma unroll
    for (int i = 0; i < 8; i++)
        #pragma unroll
        for (int j = 0; j < 8; j++) acc[i][j] = 0.f;
    int tx = tid & 15, ty = tid >> 4;

    const float* Ab = g_agg + (b*VCH)*HW + h*IMG_W;
    for (int k0 = 0; k0 < VCH; k0 += 8) {
        #pragma unroll
        for (int i = 0; i < 4; i++) {
            int kk = la_k + 2*i;
            As[kk][la_m] = Ab[(k0 + kk)*HW + la_m];
        }
        #pragma unroll
        for (int i = 0; i < 4; i++) {
            int kk = lb_k + 2*i;
            Bs[kk][lb_n] = g_owT[(k0 + kk)*MID + bn + lb_n];
        }
        __syncthreads();
        #pragma unroll
        for (int kk = 0; kk < 8; kk++) {
            float4 a0 = *(const float4*)&As[kk][ty*8];
            float4 a1 = *(const float4*)&As[kk][ty*8+4];
            float4 b0 = *(const float4*)&Bs[kk][tx*8];
            float4 b1 = *(const float4*)&Bs[kk][tx*8+4];
            float ar[8] = {a0.x,a0.y,a0.z,a0.w,a1.x,a1.y,a1.z,a1.w};
            float br[8] = {b0.x,b0.y,b0.z,b0.w,b1.x,b1.y,b1.z,b1.w};
            #pragma unroll
            for (int i = 0; i < 8; i++)
                #pragma unroll
                for (int j = 0; j < 8; j++)
                    acc[i][j] = fmaf(ar[i], br[j], acc[i][j]);
        }
        __syncthreads();
    }
    float* xb = g_x + (b*MID)*HW + h*IMG_W;
    #pragma unroll
    for (int j = 0; j < 8; j++) {
        int n = bn + tx*8 + j;
        float4* p0 = (float4*)(xb + n*HW + ty*8);
        float4* p1 = (float4*)(xb + n*HW + ty*8 + 4);
        float4 o0 = *p0, o1 = *p1;
        o0.x += acc[0][j]; o0.y += acc[1][j]; o0.z += acc[2][j]; o0.w += acc[3][j];
        o1.x += acc[4][j]; o1.y += acc[5][j]; o1.z += acc[6][j]; o1.w += acc[7][j];
        *p0 = o0; *p1 = o1;
    }
}

// ---------------- cls head ----------------
__global__ __launch_bounds__(256)
void cls_kernel(const float* __restrict__ cls_w, const float* __restrict__ cls_b,
                float* __restrict__ logits) {
    __shared__ float sw[NCLS*MID];
    __shared__ float sb[NCLS];
    int tid = threadIdx.x;
    for (int i = tid; i < NCLS*MID; i += 256) sw[i] = cls_w[i];
    if (tid < NCLS) sb[tid] = cls_b[tid];
    __syncthreads();

    int pix = blockIdx.x * 256 + tid;
    int b = pix >> 14, hw = pix & (HW-1);
    float acc[NCLS];
    #pragma unroll
    for (int k = 0; k < NCLS; k++) acc[k] = 0.f;
    const float* xb = g_x + (b*MID)*HW + hw;
    for (int c = 0; c < MID; c++) {
        float v = xb[c*HW];
        #pragma unroll
        for (int k = 0; k < NCLS; k++) acc[k] = fmaf(v, sw[k*MID + c], acc[k]);
    }
    #pragma unroll
    for (int k = 0; k < NCLS; k++)
        logits[(b*NCLS + k)*HW + hw] = acc[k] + sb[k];
}

// ---------------- launch ----------------
extern "C" void kernel_launch(void* const* d_in, const int* in_sizes, int n_in,
                              void* d_out, int out_size) {
    const float* feats = (const float*)d_in[0];
    const float* w3    = (const float*)d_in[1];
    const float* gamma = (const float*)d_in[2];
    const float* beta  = (const float*)d_in[3];
    const float* aux_w = (const float*)d_in[4];
    const float* aux_b = (const float*)d_in[5];
    const float* q_w   = (const float*)d_in[6];
    const float* k_w   = (const float*)d_in[7];
    const float* k_b   = (const float*)d_in[8];
    const float* v_w   = (const float*)d_in[9];
    const float* v_b   = (const float*)d_in[10];
    const float* out_w = (const float*)d_in[11];
    const float* cls_w = (const float*)d_in[12];
    const float* cls_b = (const float*)d_in[13];

    float* logits  = (float*)d_out;
    float* aux_out = (float*)d_out + BSZ*NCLS*HW;

    cudaFuncSetAttribute(conv_mma, cudaFuncAttributeMaxDynamicSharedMemorySize, SMEM_DYN);

    long pad4 = 2L * ((long)BSZ*PH*PW*CIN / 8);
    zero_pad<<<(int)((pad4 + 255) / 256), 256>>>();
    nhwc_prep<<<BSZ*IMG_H, 256>>>(feats);
    w3_prep<<<(9*MID*CIN + 255)/256, 256>>>(w3);
    prep_transpose<<<(MID*VCH + 255)/256, 256>>>(q_w, out_w);
    zero_kernel<<<(BSZ*NCLS*MID + 255)/256, 256>>>();
    conv_mma<<<dim3(2, BSZ*IMG_H), 256, SMEM_DYN>>>();
    bn_stats<<<MID, 256>>>(gamma, beta);
    bn_aux_softmax<<<BSZ*HW/256, 256>>>(aux_w, aux_b, aux_out);
    context_kernel<<<dim3(HW/512, BSZ), 512>>>();
    kv_kernel<<<BSZ*NCLS, 256>>>(k_w, k_b, v_w, v_b);
    gemm_q<<<dim3(KCH/128, BSZ*IMG_H), 256>>>();
    attention_kernel<<<BSZ*HW/256, 256>>>();
    gemm_obj<<<dim3(MID/128, BSZ*IMG_H), 256>>>();
    cls_kernel<<<BSZ*HW/256, 256>>>(cls_w, cls_b, logits);
}

// round 5
// speedup vs baseline: 1.4827x; 1.4827x over previous
#include <cuda_runtime.h>
#include <cuda_fp16.h>
#include <math.h>
#include <cstdint>

#define HW     16384
#define IMG_H  128
#define IMG_W  128
#define BSZ    4
#define CIN    720
#define MID    512
#define NCLS   19
#define KCH    256
#define VCH    256

#define PH 130
#define PW 130

// conv tiling (R3 structure): CTA 128x128, K-chunk 48, 8 warps (4m x 2n), warp tile 32x64
#define BM        128
#define BN        128
#define KCH_C     48
#define NCHUNKS   135         // 9 shifts * 15 chunks
#define ASTRIDE   56          // padded row length (fp16 elems)
#define REG_ELE   (128*ASTRIDE)
#define STAGE_ELE (3*REG_ELE)            // Ah, Al, Bh
#define STAGE_BYTES (STAGE_ELE*2)        // 43008
#define SMEM_DYN  (2*STAGE_BYTES)        // 86016

// ---------------- scratch ----------------
__device__ float g_x    [BSZ*MID*HW];
__device__ float g_qwT  [MID*KCH];
__device__ float g_owT  [VCH*MID];
__device__ float g_probs[BSZ*NCLS*HW];
__device__ float g_S    [BSZ*NCLS];
__device__ float g_ctx  [BSZ*NCLS*MID];
__device__ float g_kmat [BSZ*NCLS*KCH];
__device__ float g_vmat [BSZ*NCLS*VCH];
__device__ float g_q    [BSZ*HW*KCH];
__device__ float g_agg  [BSZ*VCH*HW];
__device__ float g_scale[MID];
__device__ float g_shift[MID];
// fp16 split buffers: A (feats) hi+lo, B (weights) hi only
__device__ __align__(16) __half g_fhi[BSZ*PH*PW*CIN];
__device__ __align__(16) __half g_flo[BSZ*PH*PW*CIN];
__device__ __align__(16) __half g_whi[9*MID*CIN];

// ---------------- helpers ----------------
__device__ __forceinline__ uint32_t smem_u32(const void* p) {
    uint32_t a;
    asm("{ .reg .u64 t; cvta.to.shared.u64 t, %1; cvt.u32.u64 %0, t; }" : "=r"(a) : "l"(p));
    return a;
}
__device__ __forceinline__ void cp16(uint32_t s, const void* g) {
    asm volatile("cp.async.cg.shared.global [%0], [%1], 16;" :: "r"(s), "l"(g));
}
__device__ __forceinline__ void cp_commit() {
    asm volatile("cp.async.commit_group;");
}
__device__ __forceinline__ void mma16816(float* d, const uint32_t* a, const uint32_t* b) {
    asm volatile(
        "mma.sync.aligned.m16n8k16.row.col.f32.f16.f16.f32 "
        "{%0,%1,%2,%3}, {%4,%5,%6,%7}, {%8,%9}, {%0,%1,%2,%3};"
        : "+f"(d[0]), "+f"(d[1]), "+f"(d[2]), "+f"(d[3])
        : "r"(a[0]), "r"(a[1]), "r"(a[2]), "r"(a[3]), "r"(b[0]), "r"(b[1]));
}

// ---------------- prep: zero padded fp16 buffers ----------------
__global__ void zero_pad() {
    long i = (long)blockIdx.x * 256 + threadIdx.x;
    const long n4 = (long)BSZ*PH*PW*CIN / 8;
    if (i < n4)        ((float4*)g_fhi)[i] = make_float4(0.f, 0.f, 0.f, 0.f);
    else if (i < 2*n4) ((float4*)g_flo)[i - n4] = make_float4(0.f, 0.f, 0.f, 0.f);
}

// ---------------- prep: NHWC fp16 hi/lo of feats (padded) ----------------
__global__ __launch_bounds__(256) void nhwc_prep(const float* __restrict__ feats) {
    __shared__ float tile[64][129];
    int by = blockIdx.x;
    int b = by >> 7, h = by & 127;
    int tid = threadIdx.x;
    const float* fb = feats + ((long)b * CIN) * HW + h * IMG_W;
    long obase = ((long)(b * PH + h + 1) * PW + 1) * CIN;
    for (int c0 = 0; c0 < CIN; c0 += 64) {
        int cw = CIN - c0; if (cw > 64) cw = 64;
        #pragma unroll 4
        for (int j = 0; j < 32; j++) {
            int idx = tid + j * 256;
            int c = idx >> 7, w = idx & 127;
            if (c < cw) tile[c][w] = fb[(long)(c0 + c) * HW + w];
        }
        __syncthreads();
        #pragma unroll 4
        for (int j = 0; j < 32; j++) {
            int idx = tid + j * 256;
            int w = idx >> 6, c = idx & 63;
            if (c < cw) {
                float v = tile[c][w];
                __half hi = __float2half_rn(v);
                __half lo = __float2half_rn(v - __half2float(hi));
                long o = obase + (long)w * CIN + c0 + c;
                g_fhi[o] = hi;
                g_flo[o] = lo;
            }
        }
        __syncthreads();
    }
}

// ---------------- prep: weights [r][o][c] fp16 hi ----------------
__global__ void w3_prep(const float* __restrict__ w3) {
    int e = blockIdx.x * 256 + threadIdx.x;
    if (e >= 9 * MID * CIN) return;
    int r = e / (MID * CIN);
    int rem = e - r * (MID * CIN);
    int o = rem / CIN;
    int c = rem - o * CIN;
    g_whi[e] = __float2half_rn(w3[(o * CIN + c) * 9 + r]);
}

// ---------------- zero small accumulators ----------------
__global__ void zero_kernel() {
    int i = blockIdx.x * 256 + threadIdx.x;
    if (i < BSZ*NCLS*MID) g_ctx[i] = 0.f;
    if (i < BSZ*NCLS)     g_S[i]   = 0.f;
}

// ---------------- transpose small weights ----------------
__global__ void prep_transpose(const float* __restrict__ qw, const float* __restrict__ ow) {
    int i = blockIdx.x * 256 + threadIdx.x;
    if (i < KCH*MID) {
        int d = i / MID; int c = i - d*MID;
        g_qwT[c*KCH + d] = qw[i];
    }
    if (i < MID*VCH) {
        int c = i / VCH; int v = i - c*VCH;
        g_owT[v*MID + c] = ow[i];
    }
}

// ---------------- conv3x3 via mma.sync fp16x2 (Ah*Bh + Al*Bh) ----------------
// grid (4, 512): x = 128-col output-channel block, y = (b,h). 256 threads = 8 warps (4m x 2n).
__global__ __launch_bounds__(256) void conv_mma() {
    extern __shared__ __half sm[];
    uint32_t sbase = smem_u32(sm);
    int tid = threadIdx.x;
    int lane = tid & 31, warp = tid >> 5;
    int wm = warp & 3, wn = warp >> 2;
    int qrow = lane >> 2, qcol = (lane & 3) * 2;
    int bn = blockIdx.x * BN;
    int by = blockIdx.y;
    int b = by >> 7, h = by & 127;

    const __half* fhi_b = g_fhi + (long)b * PH * PW * CIN;
    const __half* flo_b = g_flo + (long)b * PH * PW * CIN;

    // per-thread load mapping: 128 rows x 48 cols, 2 threads per row
    int lrow = tid >> 1, lhalf = tid & 1;
    int thr_g = lrow * CIN + lhalf * 24;
    uint32_t thr_s = (uint32_t)(lrow * ASTRIDE + lhalf * 24) * 2;

    float d[2][8][4];
    #pragma unroll
    for (int mt = 0; mt < 2; mt++)
        #pragma unroll
        for (int nt = 0; nt < 8; nt++)
            #pragma unroll
            for (int e = 0; e < 4; e++) d[mt][nt][e] = 0.f;

    int nr = 0, nci = 0, nc0 = 0;

    // prologue: chunk 0 -> stage 0
    {
        int ab = (0 * PW + 0) * CIN + 0 + thr_g + h * PW * CIN;   // ky=0, kx=0
        int bb = (0 * MID + bn) * CIN + 0 + thr_g;
        uint32_t st = sbase;
        #pragma unroll
        for (int j = 0; j < 3; j++) {
            cp16(st + 0*REG_ELE*2 + thr_s + j*16, fhi_b + ab + j*8);
            cp16(st + 1*REG_ELE*2 + thr_s + j*16, flo_b + ab + j*8);
            cp16(st + 2*REG_ELE*2 + thr_s + j*16, g_whi + bb + j*8);
        }
        cp_commit();
    }
    nci = 1; nc0 = KCH_C;

    for (int it = 0; it < NCHUNKS; it++) {
        int s = it & 1;
        if (it + 1 < NCHUNKS) {
            int ky = nr / 3, kx = nr - ky * 3;
            int ab = ((h + ky) * PW + kx) * CIN + nc0 + thr_g;
            int bb = (nr * MID + bn) * CIN + nc0 + thr_g;
            uint32_t st = sbase + (uint32_t)(1 - s) * STAGE_BYTES;
            #pragma unroll
            for (int j = 0; j < 3; j++) {
                cp16(st + 0*REG_ELE*2 + thr_s + j*16, fhi_b + ab + j*8);
                cp16(st + 1*REG_ELE*2 + thr_s + j*16, flo_b + ab + j*8);
                cp16(st + 2*REG_ELE*2 + thr_s + j*16, g_whi + bb + j*8);
            }
            cp_commit();
            nci++; nc0 += KCH_C;
            if (nci == 15) { nci = 0; nc0 = 0; nr++; }
            asm volatile("cp.async.wait_group 1;");
        } else {
            asm volatile("cp.async.wait_group 0;");
        }
        __syncthreads();

        const __half* st = sm + (size_t)s * STAGE_ELE;
        const __half* Ah = st;
        const __half* Al = st + REG_ELE;
        const __half* Bh = st + 2*REG_ELE;

        #pragma unroll
        for (int ks = 0; ks < 3; ks++) {
            int k0 = ks * 16 + qcol;
            uint32_t ah[2][4], al[2][4], bh[8][2];
            #pragma unroll
            for (int mt = 0; mt < 2; mt++) {
                int r0 = wm * 32 + mt * 16 + qrow;
                ah[mt][0] = *(const uint32_t*)(Ah + r0*ASTRIDE + k0);
                ah[mt][1] = *(const uint32_t*)(Ah + (r0+8)*ASTRIDE + k0);
                ah[mt][2] = *(const uint32_t*)(Ah + r0*ASTRIDE + k0 + 8);
                ah[mt][3] = *(const uint32_t*)(Ah + (r0+8)*ASTRIDE + k0 + 8);
                al[mt][0] = *(const uint32_t*)(Al + r0*ASTRIDE + k0);
                al[mt][1] = *(const uint32_t*)(Al + (r0+8)*ASTRIDE + k0);
                al[mt][2] = *(const uint32_t*)(Al + r0*ASTRIDE + k0 + 8);
                al[mt][3] = *(const uint32_t*)(Al + (r0+8)*ASTRIDE + k0 + 8);
            }
            #pragma unroll
            for (int nt = 0; nt < 8; nt++) {
                int n0 = wn * 64 + nt * 8 + qrow;
                bh[nt][0] = *(const uint32_t*)(Bh + n0*ASTRIDE + k0);
                bh[nt][1] = *(const uint32_t*)(Bh + n0*ASTRIDE + k0 + 8);
            }
            #pragma unroll
            for (int mt = 0; mt < 2; mt++)
                #pragma unroll
                for (int nt = 0; nt < 8; nt++) {
                    mma16816(d[mt][nt], ah[mt], bh[nt]);
                    mma16816(d[mt][nt], al[mt], bh[nt]);
                }
        }
        __syncthreads();
    }

    // epilogue: transpose through SMEM -> coalesced stores to g_x[n][pixel]
    float* es = (float*)sm;    // [128 n][132 m]
    #pragma unroll
    for (int mt = 0; mt < 2; mt++) {
        int m = wm * 32 + mt * 16 + qrow;
        #pragma unroll
        for (int nt = 0; nt < 8; nt++) {
            int n = wn * 64 + nt * 8 + qcol;
            es[n*132 + m]       = d[mt][nt][0];
            es[(n+1)*132 + m]   = d[mt][nt][1];
            es[n*132 + m + 8]   = d[mt][nt][2];
            es[(n+1)*132 + m+8] = d[mt][nt][3];
        }
    }
    __syncthreads();
    {
        int n = tid >> 1;
        int mh = (tid & 1) * 64;
        float* dst = g_x + ((long)(b * MID + bn + n)) * HW + h * IMG_W + mh;
        const float* src = es + n*132 + mh;
        #pragma unroll
        for (int j = 0; j < 16; j++)
            ((float4*)dst)[j] = ((const float4*)src)[j];
    }
}

// ---------------- BN stats per channel ----------------
__global__ void bn_stats(const float* __restrict__ gamma, const float* __restrict__ beta) {
    int c = blockIdx.x, tid = threadIdx.x;
    float s = 0.f, sq = 0.f;
    for (int b = 0; b < BSZ; b++) {
        const float* p = g_x + (b*MID + c)*HW;
        for (int i = tid; i < HW; i += 256) { float v = p[i]; s += v; sq += v*v; }
    }
    __shared__ float ss[256], s2[256];
    ss[tid] = s; s2[tid] = sq; __syncthreads();
    for (int st = 128; st > 0; st >>= 1) {
        if (tid < st) { ss[tid] += ss[tid+st]; s2[tid] += s2[tid+st]; }
        __syncthreads();
    }
    if (tid == 0) {
        float n    = (float)(BSZ*HW);
        float mean = ss[0] / n;
        float var  = s2[0] / n - mean*mean;
        float rstd = rsqrtf(var + 1e-5f);
        float sc   = gamma[c] * rstd;
        g_scale[c] = sc;
        g_shift[c] = beta[c] - mean * sc;
    }
}

// ---------------- fused: BN apply + relu + aux head + softmax + prob sums ----------------
__global__ __launch_bounds__(256)
void bn_aux_softmax(const float* __restrict__ aux_w, const float* __restrict__ aux_b,
                    float* __restrict__ aux_out) {
    __shared__ float sw[NCLS*MID];
    __shared__ float ssc[MID], ssh[MID];
    __shared__ float sb[NCLS], sS[NCLS];
    int tid = threadIdx.x;
    for (int i = tid; i < NCLS*MID; i += 256) sw[i] = aux_w[i];
    for (int i = tid; i < MID; i += 256) { ssc[i] = g_scale[i]; ssh[i] = g_shift[i]; }
    if (tid < NCLS) { sb[tid] = aux_b[tid]; sS[tid] = 0.f; }
    __syncthreads();

    int pix = blockIdx.x * 256 + tid;
    int b   = pix >> 14;
    int hw  = pix & (HW-1);
    float acc[NCLS];
    #pragma unroll
    for (int k = 0; k < NCLS; k++) acc[k] = 0.f;

    float* xb = g_x + (b*MID)*HW + hw;
    for (int c = 0; c < MID; c++) {
        float v = xb[c*HW];
        v = fmaf(v, ssc[c], ssh[c]);
        v = fmaxf(v, 0.f);
        xb[c*HW] = v;
        #pragma unroll
        for (int k = 0; k < NCLS; k++) acc[k] = fmaf(v, sw[k*MID + c], acc[k]);
    }
    float mx = -1e30f;
    #pragma unroll
    for (int k = 0; k < NCLS; k++) {
        acc[k] += sb[k];
        aux_out[(b*NCLS + k)*HW + hw] = acc[k];
        mx = fmaxf(mx, acc[k]);
    }
    float sum = 0.f;
    #pragma unroll
    for (int k = 0; k < NCLS; k++) { acc[k] = expf(acc[k] - mx); sum += acc[k]; }
    float inv = 1.f / sum;
    #pragma unroll
    for (int k = 0; k < NCLS; k++) {
        float p = acc[k] * inv;
        g_probs[(b*NCLS + k)*HW + hw] = p;
        atomicAdd(&sS[k], p);
    }
    __syncthreads();
    if (tid < NCLS) atomicAdd(&g_S[b*NCLS + tid], sS[tid]);
}

// ---------------- context ----------------
__global__ __launch_bounds__(512)
void context_kernel() {
    __shared__ float pw[NCLS][512];
    int b   = blockIdx.y;
    int n0  = blockIdx.x * 512;
    int tid = threadIdx.x;
    for (int k = 0; k < NCLS; k++)
        pw[k][tid] = g_probs[(b*NCLS + k)*HW + n0 + tid];
    __syncthreads();

    float acc[NCLS];
    #pragma unroll
    for (int k = 0; k < NCLS; k++) acc[k] = 0.f;
    const float* xr = g_x + (b*MID + tid)*HW + n0;
    for (int n = 0; n < 512; n += 4) {
        float4 xv = *(const float4*)(xr + n);
        float vv[4] = {xv.x, xv.y, xv.z, xv.w};
        #pragma unroll
        for (int dn = 0; dn < 4; dn++) {
            float v = vv[dn];
            #pragma unroll
            for (int k = 0; k < NCLS; k++) acc[k] = fmaf(v, pw[k][n + dn], acc[k]);
        }
    }
    #pragma unroll
    for (int k = 0; k < NCLS; k++)
        atomicAdd(&g_ctx[(b*NCLS + k)*MID + tid], acc[k]);
}

// ---------------- k,v from normalized context ----------------
__global__ __launch_bounds__(256)
void kv_kernel(const float* __restrict__ k_w, const float* __restrict__ k_b,
               const float* __restrict__ v_w, const float* __restrict__ v_b) {
    int b  = blockIdx.x / NCLS;
    int kc = blockIdx.x % NCLS;
    __shared__ float ctx[MID];
    int tid = threadIdx.x;
    float S = fmaxf(g_S[b*NCLS + kc], 1e-6f);
    float invS = 1.f / S;
    for (int i = tid; i < MID; i += 256)
        ctx[i] = g_ctx[(b*NCLS + kc)*MID + i] * invS;
    __syncthreads();

    float kk = k_b[tid], vv = v_b[tid];
    const float4* kw4 = (const float4*)(k_w + tid*MID);
    const float4* vw4 = (const float4*)(v_w + tid*MID);
    for (int c4 = 0; c4 < MID/4; c4++) {
        float4 kw = kw4[c4], vw = vw4[c4];
        float c0 = ctx[c4*4], c1 = ctx[c4*4+1], c2 = ctx[c4*4+2], c3 = ctx[c4*4+3];
        kk = fmaf(c0, kw.x, fmaf(c1, kw.y, fmaf(c2, kw.z, fmaf(c3, kw.w, kk))));
        vv = fmaf(c0, vw.x, fmaf(c1, vw.y, fmaf(c2, vw.z, fmaf(c3, vw.w, vv))));
    }
    g_kmat[(b*NCLS + kc)*KCH + tid] = kk;
    g_vmat[(b*NCLS + kc)*VCH + tid] = vv;
}

// ---------------- q = x * q_w^T ----------------
__global__ __launch_bounds__(256)
void gemm_q() {
    __shared__ float As[8][128];
    __shared__ float Bs[8][128];
    int tid = threadIdx.x;
    int bn = blockIdx.x * 128;
    int by = blockIdx.y;
    int b = by >> 7, h = by & 127;

    int la_m = tid & 127, la_k = tid >> 7;
    int lb_n = tid & 127, lb_k = tid >> 7;
    float acc[8][8];
    #pragma unroll
    for (int i = 0; i < 8; i++)
        #pragma unroll
        for (int j = 0; j < 8; j++) acc[i][j] = 0.f;
    int tx = tid & 15, ty = tid >> 4;

    const float* Ab = g_x + (b*MID)*HW + h*IMG_W;
    for (int k0 = 0; k0 < MID; k0 += 8) {
        #pragma unroll
        for (int i = 0; i < 4; i++) {
            int kk = la_k + 2*i;
            As[kk][la_m] = Ab[(k0 + kk)*HW + la_m];
        }
        #pragma unroll
        for (int i = 0; i < 4; i++) {
            int kk = lb_k + 2*i;
            Bs[kk][lb_n] = g_qwT[(k0 + kk)*KCH + bn + lb_n];
        }
        __syncthreads();
        #pragma unroll
        for (int kk = 0; kk < 8; kk++) {
            float4 a0 = *(const float4*)&As[kk][ty*8];
            float4 a1 = *(const float4*)&As[kk][ty*8+4];
            float4 b0 = *(const float4*)&Bs[kk][tx*8];
            float4 b1 = *(const float4*)&Bs[kk][tx*8+4];
            float ar[8] = {a0.x,a0.y,a0.z,a0.w,a1.x,a1.y,a1.z,a1.w};
            float br[8] = {b0.x,b0.y,b0.z,b0.w,b1.x,b1.y,b1.z,b1.w};
            #pragma unroll
            for (int i = 0; i < 8; i++)
                #pragma unroll
                for (int j = 0; j < 8; j++)
                    acc[i][j] = fmaf(ar[i], br[j], acc[i][j]);
        }
        __syncthreads();
    }
    int m0 = (b << 14) + h*IMG_W;
    #pragma unroll
    for (int i = 0; i < 8; i++) {
        int m = m0 + ty*8 + i;
        float4 v0 = make_float4(acc[i][0], acc[i][1], acc[i][2], acc[i][3]);
        float4 v1 = make_float4(acc[i][4], acc[i][5], acc[i][6], acc[i][7]);
        *(float4*)(g_q + m*KCH + bn + tx*8)     = v0;
        *(float4*)(g_q + m*KCH + bn + tx*8 + 4) = v1;
    }
}

// ---------------- attention ----------------
__global__ __launch_bounds__(256)
void attention_kernel() {
    __shared__ float ks[NCLS*KCH];
    __shared__ float vs[NCLS*VCH];
    int tid = threadIdx.x;
    int pix = blockIdx.x * 256 + tid;
    int b = pix >> 14, hw = pix & (HW-1);
    for (int i = tid; i < NCLS*KCH; i += 256) ks[i] = g_kmat[b*NCLS*KCH + i];
    for (int i = tid; i < NCLS*VCH; i += 256) vs[i] = g_vmat[b*NCLS*VCH + i];
    __syncthreads();

    float s[NCLS];
    #pragma unroll
    for (int k = 0; k < NCLS; k++) s[k] = 0.f;
    const float4* qp = (const float4*)(g_q + (long)pix*KCH);
    for (int d4 = 0; d4 < KCH/4; d4++) {
        float4 q4 = qp[d4];
        float qv[4] = {q4.x, q4.y, q4.z, q4.w};
        #pragma unroll
        for (int j = 0; j < 4; j++) {
            float q = qv[j];
            int d = d4*4 + j;
            #pragma unroll
            for (int k = 0; k < NCLS; k++) s[k] = fmaf(q, ks[k*KCH + d], s[k]);
        }
    }
    const float scale = 0.0625f;
    float mx = -1e30f;
    #pragma unroll
    for (int k = 0; k < NCLS; k++) { s[k] *= scale; mx = fmaxf(mx, s[k]); }
    float sum = 0.f;
    #pragma unroll
    for (int k = 0; k < NCLS; k++) { s[k] = expf(s[k] - mx); sum += s[k]; }
    float inv = 1.f / sum;
    #pragma unroll
    for (int k = 0; k < NCLS; k++) s[k] *= inv;

    for (int v = 0; v < VCH; v++) {
        float o = 0.f;
        #pragma unroll
        for (int k = 0; k < NCLS; k++) o = fmaf(s[k], vs[k*VCH + v], o);
        g_agg[(b*VCH + v)*HW + hw] = o;
    }
}

// ---------------- obj = agg * out_w^T, x += obj ----------------
__global__ __launch_bounds__(256)
void gemm_obj() {
    __shared__ float As[8][128];
    __shared__ float Bs[8][128];
    int tid = threadIdx.x;
    int bn = blockIdx.x * 128;
    int by = blockIdx.y;
    int b = by >> 7, h = by & 127;

    int la_m = tid & 127, la_k = tid >> 7;
    int lb_n = tid & 127, lb_k = tid >> 7;
    float acc[8][8];
    #pragma unroll
    for (int i = 0; i < 8; i++)
        #pragma unroll
        for (int j = 0; j < 8; j++) acc[i][j] = 0.f;
    int tx = tid & 15, ty = tid >> 4;

    const float* Ab = g_agg + (b*VCH)*HW + h*IMG_W;
    for (int k0 = 0; k0 < VCH; k0 += 8) {
        #pragma unroll
        for (int i = 0; i < 4; i++) {
            int kk = la_k + 2*i;
            As[kk][la_m] = Ab[(k0 + kk)*HW + la_m];
        }
        #pragma unroll
        for (int i = 0; i < 4; i++) {
            int kk = lb_k + 2*i;
            Bs[kk][lb_n] = g_owT[(k0 + kk)*MID + bn + lb_n];
        }
        __syncthreads();
        #pragma unroll
        for (int kk = 0; kk < 8; kk++) {
            float4 a0 = *(const float4*)&As[kk][ty*8];
            float4 a1 = *(const float4*)&As[kk][ty*8+4];
            float4 b0 = *(const float4*)&Bs[kk][tx*8];
            float4 b1 = *(const float4*)&Bs[kk][tx*8+4];
            float ar[8] = {a0.x,a0.y,a0.z,a0.w,a1.x,a1.y,a1.z,a1.w};
            float br[8] = {b0.x,b0.y,b0.z,b0.w,b1.x,b1.y,b1.z,b1.w};
            #pragma unroll
            for (int i = 0; i < 8; i++)
                #pragma unroll
                for (int j = 0; j < 8; j++)
                    acc[i][j] = fmaf(ar[i], br[j], acc[i][j]);
        }
        __syncthreads();
    }
    float* xb = g_x + (b*MID)*HW + h*IMG_W;
    #pragma unroll
    for (int j = 0; j < 8; j++) {
        int n = bn + tx*8 + j;
        float4* p0 = (float4*)(xb + n*HW + ty*8);
        float4* p1 = (float4*)(xb + n*HW + ty*8 + 4);
        float4 o0 = *p0, o1 = *p1;
        o0.x += acc[0][j]; o0.y += acc[1][j]; o0.z += acc[2][j]; o0.w += acc[3][j];
        o1.x += acc[4][j]; o1.y += acc[5][j]; o1.z += acc[6][j]; o1.w += acc[7][j];
        *p0 = o0; *p1 = o1;
    }
}

// ---------------- cls head ----------------
__global__ __launch_bounds__(256)
void cls_kernel(const float* __restrict__ cls_w, const float* __restrict__ cls_b,
                float* __restrict__ logits) {
    __shared__ float sw[NCLS*MID];
    __shared__ float sb[NCLS];
    int tid = threadIdx.x;
    for (int i = tid; i < NCLS*MID; i += 256) sw[i] = cls_w[i];
    if (tid < NCLS) sb[tid] = cls_b[tid];
    __syncthreads();

    int pix = blockIdx.x * 256 + tid;
    int b = pix >> 14, hw = pix & (HW-1);
    float acc[NCLS];
    #pragma unroll
    for (int k = 0; k < NCLS; k++) acc[k] = 0.f;
    const float* xb = g_x + (b*MID)*HW + hw;
    for (int c = 0; c < MID; c++) {
        float v = xb[c*HW];
        #pragma unroll
        for (int k = 0; k < NCLS; k++) acc[k] = fmaf(v, sw[k*MID + c], acc[k]);
    }
    #pragma unroll
    for (int k = 0; k < NCLS; k++)
        logits[(b*NCLS + k)*HW + hw] = acc[k] + sb[k];
}

// ---------------- launch ----------------
extern "C" void kernel_launch(void* const* d_in, const int* in_sizes, int n_in,
                              void* d_out, int out_size) {
    const float* feats = (const float*)d_in[0];
    const float* w3    = (const float*)d_in[1];
    const float* gamma = (const float*)d_in[2];
    const float* beta  = (const float*)d_in[3];
    const float* aux_w = (const float*)d_in[4];
    const float* aux_b = (const float*)d_in[5];
    const float* q_w   = (const float*)d_in[6];
    const float* k_w   = (const float*)d_in[7];
    const float* k_b   = (const float*)d_in[8];
    const float* v_w   = (const float*)d_in[9];
    const float* v_b   = (const float*)d_in[10];
    const float* out_w = (const float*)d_in[11];
    const float* cls_w = (const float*)d_in[12];
    const float* cls_b = (const float*)d_in[13];

    float* logits  = (float*)d_out;
    float* aux_out = (float*)d_out + BSZ*NCLS*HW;

    cudaFuncSetAttribute(conv_mma, cudaFuncAttributeMaxDynamicSharedMemorySize, SMEM_DYN);

    long pad4 = 2L * ((long)BSZ*PH*PW*CIN / 8);
    zero_pad<<<(int)((pad4 + 255) / 256), 256>>>();
    nhwc_prep<<<BSZ*IMG_H, 256>>>(feats);
    w3_prep<<<(9*MID*CIN + 255)/256, 256>>>(w3);
    prep_transpose<<<(MID*VCH + 255)/256, 256>>>(q_w, out_w);
    zero_kernel<<<(BSZ*NCLS*MID + 255)/256, 256>>>();
    conv_mma<<<dim3(MID/BN, BSZ*IMG_H), 256, SMEM_DYN>>>();
    bn_stats<<<MID, 256>>>(gamma, beta);
    bn_aux_softmax<<<BSZ*HW/256, 256>>>(aux_w, aux_b, aux_out);
    context_kernel<<<dim3(HW/512, BSZ), 512>>>();
    kv_kernel<<<BSZ*NCLS, 256>>>(k_w, k_b, v_w, v_b);
    gemm_q<<<dim3(KCH/128, BSZ*IMG_H), 256>>>();
    attention_kernel<<<BSZ*HW/256, 256>>>();
    gemm_obj<<<dim3(MID/128, BSZ*IMG_H), 256>>>();
    cls_kernel<<<BSZ*HW/256, 256>>>(cls_w, cls_b, logits);
}

// round 11
// speedup vs baseline: 1.6693x; 1.1258x over previous
#include <cuda_runtime.h>
#include <cuda_fp16.h>
#include <math.h>
#include <cstdint>

#define HW     16384
#define IMG_H  128
#define IMG_W  128
#define BSZ    4
#define CIN    720
#define MID    512
#define NCLS   19
#define KCH    256
#define VCH    256

#define PH 130
#define PW 130

// conv tiling (R5, proven)
#define BM        128
#define BN        128
#define KCH_C     48
#define NCHUNKS   135
#define ASTRIDE   56
#define REG_ELE   (128*ASTRIDE)
#define STAGE_ELE (3*REG_ELE)
#define STAGE_BYTES (STAGE_ELE*2)        // 43008
#define SMEM_DYN  (2*STAGE_BYTES)        // 86016

// gemm2 tiling: CTA 128(pix) x 128(n), K-chunk 32
#define G2_STR    40
#define G2_REG    (128*G2_STR)
#define G2_STAGE  (3*G2_REG*2)           // 30720
#define G2_SMEM   67584                  // max(2*G2_STAGE, 128*132*4)

// ---------------- scratch ----------------
__device__ float g_x    [BSZ*MID*HW];
__device__ float g_q    [BSZ*HW*KCH];      // q [pix][d]
__device__ float g_probs[BSZ*NCLS*HW];
__device__ float g_S    [BSZ*NCLS];
__device__ float g_ctx  [BSZ*NCLS*MID];
__device__ float g_kmat [BSZ*NCLS*KCH];
__device__ float g_vmat [BSZ*NCLS*VCH];
__device__ float g_scale[MID];
__device__ float g_shift[MID];
__device__ __align__(16) __half g_fhi[BSZ*PH*PW*CIN];
__device__ __align__(16) __half g_flo[BSZ*PH*PW*CIN];
__device__ __align__(16) __half g_whi[9*MID*CIN];
__device__ __align__(16) __half g_xh16[BSZ*HW*MID];   // x hi [pix][c]
__device__ __align__(16) __half g_xl16[BSZ*HW*MID];   // x lo [pix][c]
__device__ __align__(16) __half g_aggh[BSZ*HW*VCH];   // agg hi [pix][v]
__device__ __align__(16) __half g_aggl[BSZ*HW*VCH];   // agg lo [pix][v]
__device__ __align__(16) __half g_qw16[KCH*MID];      // q_w [d][c]
__device__ __align__(16) __half g_ow16[MID*VCH];      // out_w [o][v]

// ---------------- helpers ----------------
__device__ __forceinline__ uint32_t smem_u32(const void* p) {
    uint32_t a;
    asm("{ .reg .u64 t; cvta.to.shared.u64 t, %1; cvt.u32.u64 %0, t; }" : "=r"(a) : "l"(p));
    return a;
}
__device__ __forceinline__ void cp16(uint32_t s, const void* g) {
    asm volatile("cp.async.cg.shared.global [%0], [%1], 16;" :: "r"(s), "l"(g));
}
__device__ __forceinline__ void cp_commit() {
    asm volatile("cp.async.commit_group;");
}
__device__ __forceinline__ void mma16816(float* d, const uint32_t* a, const uint32_t* b) {
    asm volatile(
        "mma.sync.aligned.m16n8k16.row.col.f32.f16.f16.f32 "
        "{%0,%1,%2,%3}, {%4,%5,%6,%7}, {%8,%9}, {%0,%1,%2,%3};"
        : "+f"(d[0]), "+f"(d[1]), "+f"(d[2]), "+f"(d[3])
        : "r"(a[0]), "r"(a[1]), "r"(a[2]), "r"(a[3]), "r"(b[0]), "r"(b[1]));
}

// ---------------- prep: zero padded fp16 buffers ----------------
__global__ void zero_pad() {
    long i = (long)blockIdx.x * 256 + threadIdx.x;
    const long n4 = (long)BSZ*PH*PW*CIN / 8;
    if (i < n4)        ((float4*)g_fhi)[i] = make_float4(0.f, 0.f, 0.f, 0.f);
    else if (i < 2*n4) ((float4*)g_flo)[i - n4] = make_float4(0.f, 0.f, 0.f, 0.f);
}

// ---------------- prep: NHWC fp16 hi/lo of feats (padded) ----------------
__global__ __launch_bounds__(256) void nhwc_prep(const float* __restrict__ feats) {
    __shared__ float tile[64][129];
    int by = blockIdx.x;
    int b = by >> 7, h = by & 127;
    int tid = threadIdx.x;
    const float* fb = feats + ((long)b * CIN) * HW + h * IMG_W;
    long obase = ((long)(b * PH + h + 1) * PW + 1) * CIN;
    for (int c0 = 0; c0 < CIN; c0 += 64) {
        int cw = CIN - c0; if (cw > 64) cw = 64;
        #pragma unroll 4
        for (int j = 0; j < 32; j++) {
            int idx = tid + j * 256;
            int c = idx >> 7, w = idx & 127;
            if (c < cw) tile[c][w] = fb[(long)(c0 + c) * HW + w];
        }
        __syncthreads();
        #pragma unroll 4
        for (int j = 0; j < 32; j++) {
            int idx = tid + j * 256;
            int w = idx >> 6, c = idx & 63;
            if (c < cw) {
                float v = tile[c][w];
                __half hi = __float2half_rn(v);
                __half lo = __float2half_rn(v - __half2float(hi));
                long o = obase + (long)w * CIN + c0 + c;
                g_fhi[o] = hi;
                g_flo[o] = lo;
            }
        }
        __syncthreads();
    }
}

// ---------------- prep: conv weights [r][o][c] fp16 ----------------
__global__ void w3_prep(const float* __restrict__ w3) {
    int e = blockIdx.x * 256 + threadIdx.x;
    if (e >= 9 * MID * CIN) return;
    int r = e / (MID * CIN);
    int rem = e - r * (MID * CIN);
    int o = rem / CIN;
    int c = rem - o * CIN;
    g_whi[e] = __float2half_rn(w3[(o * CIN + c) * 9 + r]);
}

// ---------------- prep: q_w / out_w fp16 ----------------
__global__ void w16_prep(const float* __restrict__ qw, const float* __restrict__ ow) {
    int i = blockIdx.x * 256 + threadIdx.x;
    if (i < KCH*MID) g_qw16[i] = __float2half_rn(qw[i]);
    if (i < MID*VCH) g_ow16[i] = __float2half_rn(ow[i]);
}

// ---------------- zero small accumulators ----------------
__global__ void zero_kernel() {
    int i = blockIdx.x * 256 + threadIdx.x;
    if (i < BSZ*NCLS*MID) g_ctx[i] = 0.f;
    if (i < BSZ*NCLS)     g_S[i]   = 0.f;
}

// ---------------- conv3x3 via mma.sync fp16x2 (unchanged R5) ----------------
__global__ __launch_bounds__(256) void conv_mma() {
    extern __shared__ __half sm[];
    uint32_t sbase = smem_u32(sm);
    int tid = threadIdx.x;
    int lane = tid & 31, warp = tid >> 5;
    int wm = warp & 3, wn = warp >> 2;
    int qrow = lane >> 2, qcol = (lane & 3) * 2;
    int bn = blockIdx.x * BN;
    int by = blockIdx.y;
    int b = by >> 7, h = by & 127;

    const __half* fhi_b = g_fhi + (long)b * PH * PW * CIN;
    const __half* flo_b = g_flo + (long)b * PH * PW * CIN;

    int lrow = tid >> 1, lhalf = tid & 1;
    int thr_g = lrow * CIN + lhalf * 24;
    uint32_t thr_s = (uint32_t)(lrow * ASTRIDE + lhalf * 24) * 2;

    float d[2][8][4];
    #pragma unroll
    for (int mt = 0; mt < 2; mt++)
        #pragma unroll
        for (int nt = 0; nt < 8; nt++)
            #pragma unroll
            for (int e = 0; e < 4; e++) d[mt][nt][e] = 0.f;

    int nr = 0, nci = 0, nc0 = 0;

    {
        int ab = h * PW * CIN + thr_g;
        int bb = bn * CIN + thr_g;
        uint32_t st = sbase;
        #pragma unroll
        for (int j = 0; j < 3; j++) {
            cp16(st + 0*REG_ELE*2 + thr_s + j*16, fhi_b + ab + j*8);
            cp16(st + 1*REG_ELE*2 + thr_s + j*16, flo_b + ab + j*8);
            cp16(st + 2*REG_ELE*2 + thr_s + j*16, g_whi + bb + j*8);
        }
        cp_commit();
    }
    nci = 1; nc0 = KCH_C;

    for (int it = 0; it < NCHUNKS; it++) {
        int s = it & 1;
        if (it + 1 < NCHUNKS) {
            int ky = nr / 3, kx = nr - ky * 3;
            int ab = ((h + ky) * PW + kx) * CIN + nc0 + thr_g;
            int bb = (nr * MID + bn) * CIN + nc0 + thr_g;
            uint32_t st = sbase + (uint32_t)(1 - s) * STAGE_BYTES;
            #pragma unroll
            for (int j = 0; j < 3; j++) {
                cp16(st + 0*REG_ELE*2 + thr_s + j*16, fhi_b + ab + j*8);
                cp16(st + 1*REG_ELE*2 + thr_s + j*16, flo_b + ab + j*8);
                cp16(st + 2*REG_ELE*2 + thr_s + j*16, g_whi + bb + j*8);
            }
            cp_commit();
            nci++; nc0 += KCH_C;
            if (nci == 15) { nci = 0; nc0 = 0; nr++; }
            asm volatile("cp.async.wait_group 1;");
        } else {
            asm volatile("cp.async.wait_group 0;");
        }
        __syncthreads();

        const __half* st = sm + (size_t)s * STAGE_ELE;
        const __half* Ah = st;
        const __half* Al = st + REG_ELE;
        const __half* Bh = st + 2*REG_ELE;

        #pragma unroll
        for (int ks = 0; ks < 3; ks++) {
            int k0 = ks * 16 + qcol;
            uint32_t ah[2][4], al[2][4], bh[8][2];
            #pragma unroll
            for (int mt = 0; mt < 2; mt++) {
                int r0 = wm * 32 + mt * 16 + qrow;
                ah[mt][0] = *(const uint32_t*)(Ah + r0*ASTRIDE + k0);
                ah[mt][1] = *(const uint32_t*)(Ah + (r0+8)*ASTRIDE + k0);
                ah[mt][2] = *(const uint32_t*)(Ah + r0*ASTRIDE + k0 + 8);
                ah[mt][3] = *(const uint32_t*)(Ah + (r0+8)*ASTRIDE + k0 + 8);
                al[mt][0] = *(const uint32_t*)(Al + r0*ASTRIDE + k0);
                al[mt][1] = *(const uint32_t*)(Al + (r0+8)*ASTRIDE + k0);
                al[mt][2] = *(const uint32_t*)(Al + r0*ASTRIDE + k0 + 8);
                al[mt][3] = *(const uint32_t*)(Al + (r0+8)*ASTRIDE + k0 + 8);
            }
            #pragma unroll
            for (int nt = 0; nt < 8; nt++) {
                int n0 = wn * 64 + nt * 8 + qrow;
                bh[nt][0] = *(const uint32_t*)(Bh + n0*ASTRIDE + k0);
                bh[nt][1] = *(const uint32_t*)(Bh + n0*ASTRIDE + k0 + 8);
            }
            #pragma unroll
            for (int mt = 0; mt < 2; mt++)
                #pragma unroll
                for (int nt = 0; nt < 8; nt++) {
                    mma16816(d[mt][nt], ah[mt], bh[nt]);
                    mma16816(d[mt][nt], al[mt], bh[nt]);
                }
        }
        __syncthreads();
    }

    float* es = (float*)sm;
    #pragma unroll
    for (int mt = 0; mt < 2; mt++) {
        int m = wm * 32 + mt * 16 + qrow;
        #pragma unroll
        for (int nt = 0; nt < 8; nt++) {
            int n = wn * 64 + nt * 8 + qcol;
            es[n*132 + m]       = d[mt][nt][0];
            es[(n+1)*132 + m]   = d[mt][nt][1];
            es[n*132 + m + 8]   = d[mt][nt][2];
            es[(n+1)*132 + m+8] = d[mt][nt][3];
        }
    }
    __syncthreads();
    {
        int n = tid >> 1;
        int mh = (tid & 1) * 64;
        float* dst = g_x + ((long)(b * MID + bn + n)) * HW + h * IMG_W + mh;
        const float* src = es + n*132 + mh;
        #pragma unroll
        for (int j = 0; j < 16; j++)
            ((float4*)dst)[j] = ((const float4*)src)[j];
    }
}

// ---------------- BN stats per channel ----------------
__global__ void bn_stats(const float* __restrict__ gamma, const float* __restrict__ beta) {
    int c = blockIdx.x, tid = threadIdx.x;
    float s = 0.f, sq = 0.f;
    for (int b = 0; b < BSZ; b++) {
        const float* p = g_x + (b*MID + c)*HW;
        for (int i = tid; i < HW; i += 256) { float v = p[i]; s += v; sq += v*v; }
    }
    __shared__ float ss[256], s2[256];
    ss[tid] = s; s2[tid] = sq; __syncthreads();
    for (int st = 128; st > 0; st >>= 1) {
        if (tid < st) { ss[tid] += ss[tid+st]; s2[tid] += s2[tid+st]; }
        __syncthreads();
    }
    if (tid == 0) {
        float n    = (float)(BSZ*HW);
        float mean = ss[0] / n;
        float var  = s2[0] / n - mean*mean;
        float rstd = rsqrtf(var + 1e-5f);
        float sc   = gamma[c] * rstd;
        g_scale[c] = sc;
        g_shift[c] = beta[c] - mean * sc;
    }
}

// ---------------- fused: BN apply + relu + fp16 split emit [pix][c] + aux + softmax ----------------
__global__ __launch_bounds__(256)
void bn_aux_softmax(const float* __restrict__ aux_w, const float* __restrict__ aux_b,
                    float* __restrict__ aux_out) {
    __shared__ float sw[NCLS*MID];
    __shared__ float ssc[MID], ssh[MID];
    __shared__ float sb[NCLS], sS[NCLS];
    int tid = threadIdx.x;
    for (int i = tid; i < NCLS*MID; i += 256) sw[i] = aux_w[i];
    for (int i = tid; i < MID; i += 256) { ssc[i] = g_scale[i]; ssh[i] = g_shift[i]; }
    if (tid < NCLS) { sb[tid] = aux_b[tid]; sS[tid] = 0.f; }
    __syncthreads();

    int pix = blockIdx.x * 256 + tid;
    int b   = pix >> 14;
    int hw  = pix & (HW-1);
    float acc[NCLS];
    #pragma unroll
    for (int k = 0; k < NCLS; k++) acc[k] = 0.f;

    float* xb = g_x + (long)b * MID * HW + hw;
    long pbase = (long)pix * MID;
    for (int c0 = 0; c0 < MID; c0 += 8) {
        __align__(16) __half hb[8];
        __align__(16) __half lb[8];
        #pragma unroll
        for (int cc = 0; cc < 8; cc++) {
            int c = c0 + cc;
            float v = xb[(long)c*HW];
            v = fmaf(v, ssc[c], ssh[c]);
            v = fmaxf(v, 0.f);
            xb[(long)c*HW] = v;
            __half hv = __float2half_rn(v);
            hb[cc] = hv;
            lb[cc] = __float2half_rn(v - __half2float(hv));
            #pragma unroll
            for (int k = 0; k < NCLS; k++) acc[k] = fmaf(v, sw[k*MID + c], acc[k]);
        }
        *(uint4*)&g_xh16[pbase + c0] = *(const uint4*)hb;
        *(uint4*)&g_xl16[pbase + c0] = *(const uint4*)lb;
    }
    float mx = -1e30f;
    #pragma unroll
    for (int k = 0; k < NCLS; k++) {
        acc[k] += sb[k];
        aux_out[(b*NCLS + k)*HW + hw] = acc[k];
        mx = fmaxf(mx, acc[k]);
    }
    float sum = 0.f;
    #pragma unroll
    for (int k = 0; k < NCLS; k++) { acc[k] = expf(acc[k] - mx); sum += acc[k]; }
    float inv = 1.f / sum;
    #pragma unroll
    for (int k = 0; k < NCLS; k++) {
        float p = acc[k] * inv;
        g_probs[(b*NCLS + k)*HW + hw] = p;
        atomicAdd(&sS[k], p);
    }
    __syncthreads();
    if (tid < NCLS) atomicAdd(&g_S[b*NCLS + tid], sS[tid]);
}

// ---------------- context ----------------
__global__ __launch_bounds__(512)
void context_kernel() {
    __shared__ float pw[NCLS][512];
    int b   = blockIdx.y;
    int n0  = blockIdx.x * 512;
    int tid = threadIdx.x;
    for (int k = 0; k < NCLS; k++)
        pw[k][tid] = g_probs[(b*NCLS + k)*HW + n0 + tid];
    __syncthreads();

    float acc[NCLS];
    #pragma unroll
    for (int k = 0; k < NCLS; k++) acc[k] = 0.f;
    const float* xr = g_x + (b*MID + tid)*HW + n0;
    for (int n = 0; n < 512; n += 4) {
        float4 xv = *(const float4*)(xr + n);
        float vv[4] = {xv.x, xv.y, xv.z, xv.w};
        #pragma unroll
        for (int dn = 0; dn < 4; dn++) {
            float v = vv[dn];
            #pragma unroll
            for (int k = 0; k < NCLS; k++) acc[k] = fmaf(v, pw[k][n + dn], acc[k]);
        }
    }
    #pragma unroll
    for (int k = 0; k < NCLS; k++)
        atomicAdd(&g_ctx[(b*NCLS + k)*MID + tid], acc[k]);
}

// ---------------- k,v from normalized context ----------------
__global__ __launch_bounds__(256)
void kv_kernel(const float* __restrict__ k_w, const float* __restrict__ k_b,
               const float* __restrict__ v_w, const float* __restrict__ v_b) {
    int b  = blockIdx.x / NCLS;
    int kc = blockIdx.x % NCLS;
    __shared__ float ctx[MID];
    int tid = threadIdx.x;
    float S = fmaxf(g_S[b*NCLS + kc], 1e-6f);
    float invS = 1.f / S;
    for (int i = tid; i < MID; i += 256)
        ctx[i] = g_ctx[(b*NCLS + kc)*MID + i] * invS;
    __syncthreads();

    float kk = k_b[tid], vv = v_b[tid];
    const float4* kw4 = (const float4*)(k_w + tid*MID);
    const float4* vw4 = (const float4*)(v_w + tid*MID);
    for (int c4 = 0; c4 < MID/4; c4++) {
        float4 kw = kw4[c4], vw = vw4[c4];
        float c0 = ctx[c4*4], c1 = ctx[c4*4+1], c2 = ctx[c4*4+2], c3 = ctx[c4*4+3];
        kk = fmaf(c0, kw.x, fmaf(c1, kw.y, fmaf(c2, kw.z, fmaf(c3, kw.w, kk))));
        vv = fmaf(c0, vw.x, fmaf(c1, vw.y, fmaf(c2, vw.z, fmaf(c3, vw.w, vv))));
    }
    g_kmat[(b*NCLS + kc)*KCH + tid] = kk;
    g_vmat[(b*NCLS + kc)*VCH + tid] = vv;
}

// ---------------- gemm2 body: out[pix][n] = (Ah+Al)[pix][K] x Bw[n][K]^T ----------------
// Pointers are bound in DEVICE code by the wrapper kernels (never host-passed symbols).
__device__ __forceinline__
void gemm2_body(const __half* __restrict__ Ahp, const __half* __restrict__ Alp,
                const __half* __restrict__ Bwp, int K, int Nst,
                float* __restrict__ outp, int mode, char* smc)
{
    uint32_t sbase = smem_u32(smc);
    int tid = threadIdx.x;
    int lane = tid & 31, warp = tid >> 5;
    int wm = warp & 3, wn = warp >> 2;
    int qrow = lane >> 2, qcol = (lane & 3) * 2;
    int n0 = blockIdx.x * 128;
    long pix0 = (long)blockIdx.y * 128;

    int arow = tid >> 1, ahalf = tid & 1;
    const __half* Abh = Ahp + (pix0 + arow) * K + ahalf * 16;
    const __half* Abl = Alp + (pix0 + arow) * K + ahalf * 16;
    const __half* Bb  = Bwp + (long)(n0 + arow) * K + ahalf * 16;
    uint32_t soff = (uint32_t)(arow * G2_STR + ahalf * 16) * 2;

    float d[2][8][4];
    #pragma unroll
    for (int mt = 0; mt < 2; mt++)
        #pragma unroll
        for (int nt = 0; nt < 8; nt++)
            #pragma unroll
            for (int e = 0; e < 4; e++) d[mt][nt][e] = 0.f;

    int nCh = K >> 5;
    {
        uint32_t st = sbase;
        cp16(st + soff,                Abh);  cp16(st + soff + 16,                Abh + 8);
        cp16(st + G2_REG*2 + soff,     Abl);  cp16(st + G2_REG*2 + soff + 16,     Abl + 8);
        cp16(st + 2*G2_REG*2 + soff,   Bb);   cp16(st + 2*G2_REG*2 + soff + 16,   Bb + 8);
        cp_commit();
    }
    for (int it = 0; it < nCh; it++) {
        int s = it & 1;
        if (it + 1 < nCh) {
            int c0 = (it + 1) * 32;
            uint32_t st = sbase + (uint32_t)(1 - s) * G2_STAGE;
            cp16(st + soff,              Abh + c0);  cp16(st + soff + 16,              Abh + c0 + 8);
            cp16(st + G2_REG*2 + soff,   Abl + c0);  cp16(st + G2_REG*2 + soff + 16,   Abl + c0 + 8);
            cp16(st + 2*G2_REG*2 + soff, Bb + c0);   cp16(st + 2*G2_REG*2 + soff + 16, Bb + c0 + 8);
            cp_commit();
            asm volatile("cp.async.wait_group 1;");
        } else {
            asm volatile("cp.async.wait_group 0;");
        }
        __syncthreads();

        const __half* sp = (const __half*)(smc + (size_t)s * G2_STAGE);
        const __half* Ah = sp;
        const __half* Al = sp + G2_REG;
        const __half* Bh = sp + 2*G2_REG;

        #pragma unroll
        for (int ks = 0; ks < 2; ks++) {
            int k0 = ks * 16 + qcol;
            uint32_t a[2][4], al[2][4], bh[8][2];
            #pragma unroll
            for (int mt = 0; mt < 2; mt++) {
                int r0 = wm * 32 + mt * 16 + qrow;
                a[mt][0] = *(const uint32_t*)(Ah + r0*G2_STR + k0);
                a[mt][1] = *(const uint32_t*)(Ah + (r0+8)*G2_STR + k0);
                a[mt][2] = *(const uint32_t*)(Ah + r0*G2_STR + k0 + 8);
                a[mt][3] = *(const uint32_t*)(Ah + (r0+8)*G2_STR + k0 + 8);
                al[mt][0] = *(const uint32_t*)(Al + r0*G2_STR + k0);
                al[mt][1] = *(const uint32_t*)(Al + (r0+8)*G2_STR + k0);
                al[mt][2] = *(const uint32_t*)(Al + r0*G2_STR + k0 + 8);
                al[mt][3] = *(const uint32_t*)(Al + (r0+8)*G2_STR + k0 + 8);
            }
            #pragma unroll
            for (int nt = 0; nt < 8; nt++) {
                int nn = wn * 64 + nt * 8 + qrow;
                bh[nt][0] = *(const uint32_t*)(Bh + nn*G2_STR + k0);
                bh[nt][1] = *(const uint32_t*)(Bh + nn*G2_STR + k0 + 8);
            }
            #pragma unroll
            for (int mt = 0; mt < 2; mt++)
                #pragma unroll
                for (int nt = 0; nt < 8; nt++) {
                    mma16816(d[mt][nt], a[mt], bh[nt]);
                    mma16816(d[mt][nt], al[mt], bh[nt]);
                }
        }
        __syncthreads();
    }

    if (mode == 0) {
        #pragma unroll
        for (int mt = 0; mt < 2; mt++) {
            long r = pix0 + wm * 32 + mt * 16 + qrow;
            #pragma unroll
            for (int nt = 0; nt < 8; nt++) {
                int ncol = n0 + wn * 64 + nt * 8 + qcol;
                float* p0 = outp + r * Nst + ncol;
                float* p1 = p0 + (long)8 * Nst;
                *(float2*)p0 = make_float2(d[mt][nt][0], d[mt][nt][1]);
                *(float2*)p1 = make_float2(d[mt][nt][2], d[mt][nt][3]);
            }
        }
    } else {
        float* es = (float*)smc;
        #pragma unroll
        for (int mt = 0; mt < 2; mt++) {
            int m = wm * 32 + mt * 16 + qrow;
            #pragma unroll
            for (int nt = 0; nt < 8; nt++) {
                int n = wn * 64 + nt * 8 + qcol;
                es[n*132 + m]       = d[mt][nt][0];
                es[(n+1)*132 + m]   = d[mt][nt][1];
                es[n*132 + m + 8]   = d[mt][nt][2];
                es[(n+1)*132 + m+8] = d[mt][nt][3];
            }
        }
        __syncthreads();
        int n = tid >> 1;
        int mh = (tid & 1) * 64;
        int b = (int)(pix0 >> 14);
        int hw0 = (int)(pix0 & (HW-1));
        float* dst = outp + ((long)(b * MID + n0 + n)) * HW + hw0 + mh;
        const float* src = es + n*132 + mh;
        #pragma unroll
        for (int j = 0; j < 16; j++) {
            float4 o = ((float4*)dst)[j];
            float4 a = ((const float4*)src)[j];
            o.x += a.x; o.y += a.y; o.z += a.z; o.w += a.w;
            ((float4*)dst)[j] = o;
        }
    }
}

// wrapper kernels: bind device-global pointers IN DEVICE CODE
__global__ void __launch_bounds__(256) gemm2_q() {
    extern __shared__ char smc[];
    gemm2_body(g_xh16, g_xl16, g_qw16, MID, KCH, g_q, 0, smc);
}
__global__ void __launch_bounds__(256) gemm2_obj() {
    extern __shared__ char smc[];
    gemm2_body(g_aggh, g_aggl, g_ow16, VCH, 0, g_x, 1, smc);
}

// ---------------- attention: reads q[pix][d], writes agg fp16 hi/lo [pix][v] ----------------
__global__ __launch_bounds__(256)
void attention_kernel() {
    __shared__ float ks[NCLS*KCH];
    __shared__ float vs[NCLS*VCH];
    int tid = threadIdx.x;
    int pix = blockIdx.x * 256 + tid;
    int b = pix >> 14;
    for (int i = tid; i < NCLS*KCH; i += 256) ks[i] = g_kmat[b*NCLS*KCH + i];
    for (int i = tid; i < NCLS*VCH; i += 256) vs[i] = g_vmat[b*NCLS*VCH + i];
    __syncthreads();

    float s[NCLS];
    #pragma unroll
    for (int k = 0; k < NCLS; k++) s[k] = 0.f;
    const float4* qp = (const float4*)(g_q + (long)pix * KCH);
    for (int d4 = 0; d4 < KCH/4; d4++) {
        float4 q4 = qp[d4];
        float qv[4] = {q4.x, q4.y, q4.z, q4.w};
        #pragma unroll
        for (int j = 0; j < 4; j++) {
            float q = qv[j];
            int d = d4*4 + j;
            #pragma unroll
            for (int k = 0; k < NCLS; k++) s[k] = fmaf(q, ks[k*KCH + d], s[k]);
        }
    }
    const float scale = 0.0625f;
    float mx = -1e30f;
    #pragma unroll
    for (int k = 0; k < NCLS; k++) { s[k] *= scale; mx = fmaxf(mx, s[k]); }
    float sum = 0.f;
    #pragma unroll
    for (int k = 0; k < NCLS; k++) { s[k] = expf(s[k] - mx); sum += s[k]; }
    float inv = 1.f / sum;
    #pragma unroll
    for (int k = 0; k < NCLS; k++) s[k] *= inv;

    long pbase = (long)pix * VCH;
    for (int v0 = 0; v0 < VCH; v0 += 8) {
        __align__(16) __half hb[8];
        __align__(16) __half lb[8];
        #pragma unroll
        for (int vv = 0; vv < 8; vv++) {
            int v = v0 + vv;
            float o = 0.f;
            #pragma unroll
            for (int k = 0; k < NCLS; k++) o = fmaf(s[k], vs[k*VCH + v], o);
            __half h = __float2half_rn(o);
            hb[vv] = h;
            lb[vv] = __float2half_rn(o - __half2float(h));
        }
        *(uint4*)&g_aggh[pbase + v0] = *(const uint4*)hb;
        *(uint4*)&g_aggl[pbase + v0] = *(const uint4*)lb;
    }
}

// ---------------- cls head ----------------
__global__ __launch_bounds__(256)
void cls_kernel(const float* __restrict__ cls_w, const float* __restrict__ cls_b,
                float* __restrict__ logits) {
    __shared__ float sw[NCLS*MID];
    __shared__ float sb[NCLS];
    int tid = threadIdx.x;
    for (int i = tid; i < NCLS*MID; i += 256) sw[i] = cls_w[i];
    if (tid < NCLS) sb[tid] = cls_b[tid];
    __syncthreads();

    int pix = blockIdx.x * 256 + tid;
    int b = pix >> 14, hw = pix & (HW-1);
    float acc[NCLS];
    #pragma unroll
    for (int k = 0; k < NCLS; k++) acc[k] = 0.f;
    const float* xb = g_x + (long)b * MID * HW + hw;
    for (int c = 0; c < MID; c++) {
        float v = xb[(long)c*HW];
        #pragma unroll
        for (int k = 0; k < NCLS; k++) acc[k] = fmaf(v, sw[k*MID + c], acc[k]);
    }
    #pragma unroll
    for (int k = 0; k < NCLS; k++)
        logits[(b*NCLS + k)*HW + hw] = acc[k] + sb[k];
}

// ---------------- launch ----------------
extern "C" void kernel_launch(void* const* d_in, const int* in_sizes, int n_in,
                              void* d_out, int out_size) {
    const float* feats = (const float*)d_in[0];
    const float* w3    = (const float*)d_in[1];
    const float* gamma = (const float*)d_in[2];
    const float* beta  = (const float*)d_in[3];
    const float* aux_w = (const float*)d_in[4];
    const float* aux_b = (const float*)d_in[5];
    const float* q_w   = (const float*)d_in[6];
    const float* k_w   = (const float*)d_in[7];
    const float* k_b   = (const float*)d_in[8];
    const float* v_w   = (const float*)d_in[9];
    const float* v_b   = (const float*)d_in[10];
    const float* out_w = (const float*)d_in[11];
    const float* cls_w = (const float*)d_in[12];
    const float* cls_b = (const float*)d_in[13];

    float* logits  = (float*)d_out;
    float* aux_out = (float*)d_out + BSZ*NCLS*HW;

    cudaFuncSetAttribute(conv_mma, cudaFuncAttributeMaxDynamicSharedMemorySize, SMEM_DYN);
    cudaFuncSetAttribute(gemm2_q,   cudaFuncAttributeMaxDynamicSharedMemorySize, G2_SMEM);
    cudaFuncSetAttribute(gemm2_obj, cudaFuncAttributeMaxDynamicSharedMemorySize, G2_SMEM);

    long pad4 = 2L * ((long)BSZ*PH*PW*CIN / 8);
    zero_pad<<<(int)((pad4 + 255) / 256), 256>>>();
    nhwc_prep<<<BSZ*IMG_H, 256>>>(feats);
    w3_prep<<<(9*MID*CIN + 255)/256, 256>>>(w3);
    w16_prep<<<(MID*VCH + 255)/256, 256>>>(q_w, out_w);
    zero_kernel<<<(BSZ*NCLS*MID + 255)/256, 256>>>();
    conv_mma<<<dim3(MID/BN, BSZ*IMG_H), 256, SMEM_DYN>>>();
    bn_stats<<<MID, 256>>>(gamma, beta);
    bn_aux_softmax<<<BSZ*HW/256, 256>>>(aux_w, aux_b, aux_out);
    context_kernel<<<dim3(HW/512, BSZ), 512>>>();
    kv_kernel<<<BSZ*NCLS, 256>>>(k_w, k_b, v_w, v_b);
    gemm2_q<<<dim3(KCH/128, BSZ*HW/128), 256, G2_SMEM>>>();
    attention_kernel<<<BSZ*HW/256, 256>>>();
    gemm2_obj<<<dim3(MID/128, BSZ*HW/128), 256, G2_SMEM>>>();
    cls_kernel<<<BSZ*HW/256, 256>>>(cls_w, cls_b, logits);
}

// round 12
// speedup vs baseline: 2.2864x; 1.3697x over previous
#include <cuda_runtime.h>
#include <cuda_fp16.h>
#include <math.h>
#include <cstdint>

#define HW     16384
#define IMG_H  128
#define IMG_W  128
#define BSZ    4
#define CIN    720
#define MID    512
#define NCLS   19
#define KCH    256
#define VCH    256

#define PH 130
#define PW 130

// conv tiling: CTA 128x128, K-chunk 48, 8 warps (4m x 2n), warp tile 32x64
// SINGLE fp16 term: stage = {A, B} only
#define BM        128
#define BN        128
#define KCH_C     48
#define NCHUNKS   135
#define ASTRIDE   56
#define REG_ELE   (128*ASTRIDE)
#define STAGE_ELE (2*REG_ELE)            // A, B
#define STAGE_BYTES (STAGE_ELE*2)        // 28672
#define SMEM_DYN  67584                  // max(2*STAGE_BYTES=57344, epilogue 128*132*4)

// gemm2 tiling: CTA 128(pix) x 128(n), K-chunk 32 (2-term split, proven R11)
#define G2_STR    40
#define G2_REG    (128*G2_STR)
#define G2_STAGE  (3*G2_REG*2)           // 30720
#define G2_SMEM   67584

// ---------------- scratch ----------------
__device__ float g_x    [BSZ*MID*HW];
__device__ float g_q    [BSZ*HW*KCH];      // q [pix][d]
__device__ float g_probs[BSZ*NCLS*HW];
__device__ float g_S    [BSZ*NCLS];
__device__ float g_ctx  [BSZ*NCLS*MID];
__device__ float g_kmat [BSZ*NCLS*KCH];
__device__ float g_vmat [BSZ*NCLS*VCH];
__device__ float g_scale[MID];
__device__ float g_shift[MID];
__device__ __align__(16) __half g_fhi[BSZ*PH*PW*CIN];
__device__ __align__(16) __half g_whi[9*MID*CIN];
__device__ __align__(16) __half g_xh16[BSZ*HW*MID];   // x hi [pix][c]
__device__ __align__(16) __half g_xl16[BSZ*HW*MID];   // x lo [pix][c]
__device__ __align__(16) __half g_aggh[BSZ*HW*VCH];   // agg hi [pix][v]
__device__ __align__(16) __half g_aggl[BSZ*HW*VCH];   // agg lo [pix][v]
__device__ __align__(16) __half g_qw16[KCH*MID];      // q_w [d][c]
__device__ __align__(16) __half g_ow16[MID*VCH];      // out_w [o][v]

// ---------------- helpers ----------------
__device__ __forceinline__ uint32_t smem_u32(const void* p) {
    uint32_t a;
    asm("{ .reg .u64 t; cvta.to.shared.u64 t, %1; cvt.u32.u64 %0, t; }" : "=r"(a) : "l"(p));
    return a;
}
__device__ __forceinline__ void cp16(uint32_t s, const void* g) {
    asm volatile("cp.async.cg.shared.global [%0], [%1], 16;" :: "r"(s), "l"(g));
}
__device__ __forceinline__ void cp_commit() {
    asm volatile("cp.async.commit_group;");
}
__device__ __forceinline__ void mma16816(float* d, const uint32_t* a, const uint32_t* b) {
    asm volatile(
        "mma.sync.aligned.m16n8k16.row.col.f32.f16.f16.f32 "
        "{%0,%1,%2,%3}, {%4,%5,%6,%7}, {%8,%9}, {%0,%1,%2,%3};"
        : "+f"(d[0]), "+f"(d[1]), "+f"(d[2]), "+f"(d[3])
        : "r"(a[0]), "r"(a[1]), "r"(a[2]), "r"(a[3]), "r"(b[0]), "r"(b[1]));
}

// ---------------- prep: zero padded fp16 buffer ----------------
__global__ void zero_pad() {
    long i = (long)blockIdx.x * 256 + threadIdx.x;
    const long n4 = (long)BSZ*PH*PW*CIN / 8;
    if (i < n4) ((float4*)g_fhi)[i] = make_float4(0.f, 0.f, 0.f, 0.f);
}

// ---------------- prep: NHWC fp16 of feats (padded) ----------------
__global__ __launch_bounds__(256) void nhwc_prep(const float* __restrict__ feats) {
    __shared__ float tile[64][129];
    int by = blockIdx.x;
    int b = by >> 7, h = by & 127;
    int tid = threadIdx.x;
    const float* fb = feats + ((long)b * CIN) * HW + h * IMG_W;
    long obase = ((long)(b * PH + h + 1) * PW + 1) * CIN;
    for (int c0 = 0; c0 < CIN; c0 += 64) {
        int cw = CIN - c0; if (cw > 64) cw = 64;
        #pragma unroll 4
        for (int j = 0; j < 32; j++) {
            int idx = tid + j * 256;
            int c = idx >> 7, w = idx & 127;
            if (c < cw) tile[c][w] = fb[(long)(c0 + c) * HW + w];
        }
        __syncthreads();
        #pragma unroll 4
        for (int j = 0; j < 32; j++) {
            int idx = tid + j * 256;
            int w = idx >> 6, c = idx & 63;
            if (c < cw)
                g_fhi[obase + (long)w * CIN + c0 + c] = __float2half_rn(tile[c][w]);
        }
        __syncthreads();
    }
}

// ---------------- prep: conv weights [r][o][c] fp16 ----------------
__global__ void w3_prep(const float* __restrict__ w3) {
    int e = blockIdx.x * 256 + threadIdx.x;
    if (e >= 9 * MID * CIN) return;
    int r = e / (MID * CIN);
    int rem = e - r * (MID * CIN);
    int o = rem / CIN;
    int c = rem - o * CIN;
    g_whi[e] = __float2half_rn(w3[(o * CIN + c) * 9 + r]);
}

// ---------------- prep: q_w / out_w fp16 ----------------
__global__ void w16_prep(const float* __restrict__ qw, const float* __restrict__ ow) {
    int i = blockIdx.x * 256 + threadIdx.x;
    if (i < KCH*MID) g_qw16[i] = __float2half_rn(qw[i]);
    if (i < MID*VCH) g_ow16[i] = __float2half_rn(ow[i]);
}

// ---------------- zero small accumulators ----------------
__global__ void zero_kernel() {
    int i = blockIdx.x * 256 + threadIdx.x;
    if (i < BSZ*NCLS*MID) g_ctx[i] = 0.f;
    if (i < BSZ*NCLS)     g_S[i]   = 0.f;
}

// ---------------- conv3x3 via mma.sync, single fp16 term ----------------
__global__ __launch_bounds__(256) void conv_mma() {
    extern __shared__ __half sm[];
    uint32_t sbase = smem_u32(sm);
    int tid = threadIdx.x;
    int lane = tid & 31, warp = tid >> 5;
    int wm = warp & 3, wn = warp >> 2;
    int qrow = lane >> 2, qcol = (lane & 3) * 2;
    int bn = blockIdx.x * BN;
    int by = blockIdx.y;
    int b = by >> 7, h = by & 127;

    const __half* fhi_b = g_fhi + (long)b * PH * PW * CIN;

    int lrow = tid >> 1, lhalf = tid & 1;
    int thr_g = lrow * CIN + lhalf * 24;
    uint32_t thr_s = (uint32_t)(lrow * ASTRIDE + lhalf * 24) * 2;

    float d[2][8][4];
    #pragma unroll
    for (int mt = 0; mt < 2; mt++)
        #pragma unroll
        for (int nt = 0; nt < 8; nt++)
            #pragma unroll
            for (int e = 0; e < 4; e++) d[mt][nt][e] = 0.f;

    int nr = 0, nci = 0, nc0 = 0;

    {
        int ab = h * PW * CIN + thr_g;
        int bb = bn * CIN + thr_g;
        uint32_t st = sbase;
        #pragma unroll
        for (int j = 0; j < 3; j++) {
            cp16(st + thr_s + j*16,              fhi_b + ab + j*8);
            cp16(st + REG_ELE*2 + thr_s + j*16,  g_whi + bb + j*8);
        }
        cp_commit();
    }
    nci = 1; nc0 = KCH_C;

    for (int it = 0; it < NCHUNKS; it++) {
        int s = it & 1;
        if (it + 1 < NCHUNKS) {
            int ky = nr / 3, kx = nr - ky * 3;
            int ab = ((h + ky) * PW + kx) * CIN + nc0 + thr_g;
            int bb = (nr * MID + bn) * CIN + nc0 + thr_g;
            uint32_t st = sbase + (uint32_t)(1 - s) * STAGE_BYTES;
            #pragma unroll
            for (int j = 0; j < 3; j++) {
                cp16(st + thr_s + j*16,             fhi_b + ab + j*8);
                cp16(st + REG_ELE*2 + thr_s + j*16, g_whi + bb + j*8);
            }
            cp_commit();
            nci++; nc0 += KCH_C;
            if (nci == 15) { nci = 0; nc0 = 0; nr++; }
            asm volatile("cp.async.wait_group 1;");
        } else {
            asm volatile("cp.async.wait_group 0;");
        }
        __syncthreads();

        const __half* st = sm + (size_t)s * STAGE_ELE;
        const __half* Ah = st;
        const __half* Bh = st + REG_ELE;

        #pragma unroll
        for (int ks = 0; ks < 3; ks++) {
            int k0 = ks * 16 + qcol;
            uint32_t ah[2][4], bh[8][2];
            #pragma unroll
            for (int mt = 0; mt < 2; mt++) {
                int r0 = wm * 32 + mt * 16 + qrow;
                ah[mt][0] = *(const uint32_t*)(Ah + r0*ASTRIDE + k0);
                ah[mt][1] = *(const uint32_t*)(Ah + (r0+8)*ASTRIDE + k0);
                ah[mt][2] = *(const uint32_t*)(Ah + r0*ASTRIDE + k0 + 8);
                ah[mt][3] = *(const uint32_t*)(Ah + (r0+8)*ASTRIDE + k0 + 8);
            }
            #pragma unroll
            for (int nt = 0; nt < 8; nt++) {
                int n0 = wn * 64 + nt * 8 + qrow;
                bh[nt][0] = *(const uint32_t*)(Bh + n0*ASTRIDE + k0);
                bh[nt][1] = *(const uint32_t*)(Bh + n0*ASTRIDE + k0 + 8);
            }
            #pragma unroll
            for (int mt = 0; mt < 2; mt++)
                #pragma unroll
                for (int nt = 0; nt < 8; nt++)
                    mma16816(d[mt][nt], ah[mt], bh[nt]);
        }
        __syncthreads();
    }

    float* es = (float*)sm;
    #pragma unroll
    for (int mt = 0; mt < 2; mt++) {
        int m = wm * 32 + mt * 16 + qrow;
        #pragma unroll
        for (int nt = 0; nt < 8; nt++) {
            int n = wn * 64 + nt * 8 + qcol;
            es[n*132 + m]       = d[mt][nt][0];
            es[(n+1)*132 + m]   = d[mt][nt][1];
            es[n*132 + m + 8]   = d[mt][nt][2];
            es[(n+1)*132 + m+8] = d[mt][nt][3];
        }
    }
    __syncthreads();
    {
        int n = tid >> 1;
        int mh = (tid & 1) * 64;
        float* dst = g_x + ((long)(b * MID + bn + n)) * HW + h * IMG_W + mh;
        const float* src = es + n*132 + mh;
        #pragma unroll
        for (int j = 0; j < 16; j++)
            ((float4*)dst)[j] = ((const float4*)src)[j];
    }
}

// ---------------- BN stats per channel ----------------
__global__ void bn_stats(const float* __restrict__ gamma, const float* __restrict__ beta) {
    int c = blockIdx.x, tid = threadIdx.x;
    float s = 0.f, sq = 0.f;
    for (int b = 0; b < BSZ; b++) {
        const float* p = g_x + (b*MID + c)*HW;
        for (int i = tid; i < HW; i += 256) { float v = p[i]; s += v; sq += v*v; }
    }
    __shared__ float ss[256], s2[256];
    ss[tid] = s; s2[tid] = sq; __syncthreads();
    for (int st = 128; st > 0; st >>= 1) {
        if (tid < st) { ss[tid] += ss[tid+st]; s2[tid] += s2[tid+st]; }
        __syncthreads();
    }
    if (tid == 0) {
        float n    = (float)(BSZ*HW);
        float mean = ss[0] / n;
        float var  = s2[0] / n - mean*mean;
        float rstd = rsqrtf(var + 1e-5f);
        float sc   = gamma[c] * rstd;
        g_scale[c] = sc;
        g_shift[c] = beta[c] - mean * sc;
    }
}

// ---------------- fused: BN apply + relu + fp16 split emit [pix][c] + aux + softmax ----------------
__global__ __launch_bounds__(256)
void bn_aux_softmax(const float* __restrict__ aux_w, const float* __restrict__ aux_b,
                    float* __restrict__ aux_out) {
    __shared__ float sw[NCLS*MID];
    __shared__ float ssc[MID], ssh[MID];
    __shared__ float sb[NCLS], sS[NCLS];
    int tid = threadIdx.x;
    for (int i = tid; i < NCLS*MID; i += 256) sw[i] = aux_w[i];
    for (int i = tid; i < MID; i += 256) { ssc[i] = g_scale[i]; ssh[i] = g_shift[i]; }
    if (tid < NCLS) { sb[tid] = aux_b[tid]; sS[tid] = 0.f; }
    __syncthreads();

    int pix = blockIdx.x * 256 + tid;
    int b   = pix >> 14;
    int hw  = pix & (HW-1);
    float acc[NCLS];
    #pragma unroll
    for (int k = 0; k < NCLS; k++) acc[k] = 0.f;

    float* xb = g_x + (long)b * MID * HW + hw;
    long pbase = (long)pix * MID;
    for (int c0 = 0; c0 < MID; c0 += 8) {
        __align__(16) __half hb[8];
        __align__(16) __half lb[8];
        #pragma unroll
        for (int cc = 0; cc < 8; cc++) {
            int c = c0 + cc;
            float v = xb[(long)c*HW];
            v = fmaf(v, ssc[c], ssh[c]);
            v = fmaxf(v, 0.f);
            xb[(long)c*HW] = v;
            __half hv = __float2half_rn(v);
            hb[cc] = hv;
            lb[cc] = __float2half_rn(v - __half2float(hv));
            #pragma unroll
            for (int k = 0; k < NCLS; k++) acc[k] = fmaf(v, sw[k*MID + c], acc[k]);
        }
        *(uint4*)&g_xh16[pbase + c0] = *(const uint4*)hb;
        *(uint4*)&g_xl16[pbase + c0] = *(const uint4*)lb;
    }
    float mx = -1e30f;
    #pragma unroll
    for (int k = 0; k < NCLS; k++) {
        acc[k] += sb[k];
        aux_out[(b*NCLS + k)*HW + hw] = acc[k];
        mx = fmaxf(mx, acc[k]);
    }
    float sum = 0.f;
    #pragma unroll
    for (int k = 0; k < NCLS; k++) { acc[k] = expf(acc[k] - mx); sum += acc[k]; }
    float inv = 1.f / sum;
    #pragma unroll
    for (int k = 0; k < NCLS; k++) {
        float p = acc[k] * inv;
        g_probs[(b*NCLS + k)*HW + hw] = p;
        atomicAdd(&sS[k], p);
    }
    __syncthreads();
    if (tid < NCLS) atomicAdd(&g_S[b*NCLS + tid], sS[tid]);
}

// ---------------- context ----------------
__global__ __launch_bounds__(512)
void context_kernel() {
    __shared__ float pw[NCLS][512];
    int b   = blockIdx.y;
    int n0  = blockIdx.x * 512;
    int tid = threadIdx.x;
    for (int k = 0; k < NCLS; k++)
        pw[k][tid] = g_probs[(b*NCLS + k)*HW + n0 + tid];
    __syncthreads();

    float acc[NCLS];
    #pragma unroll
    for (int k = 0; k < NCLS; k++) acc[k] = 0.f;
    const float* xr = g_x + (b*MID + tid)*HW + n0;
    for (int n = 0; n < 512; n += 4) {
        float4 xv = *(const float4*)(xr + n);
        float vv[4] = {xv.x, xv.y, xv.z, xv.w};
        #pragma unroll
        for (int dn = 0; dn < 4; dn++) {
            float v = vv[dn];
            #pragma unroll
            for (int k = 0; k < NCLS; k++) acc[k] = fmaf(v, pw[k][n + dn], acc[k]);
        }
    }
    #pragma unroll
    for (int k = 0; k < NCLS; k++)
        atomicAdd(&g_ctx[(b*NCLS + k)*MID + tid], acc[k]);
}

// ---------------- k,v from normalized context ----------------
__global__ __launch_bounds__(256)
void kv_kernel(const float* __restrict__ k_w, const float* __restrict__ k_b,
               const float* __restrict__ v_w, const float* __restrict__ v_b) {
    int b  = blockIdx.x / NCLS;
    int kc = blockIdx.x % NCLS;
    __shared__ float ctx[MID];
    int tid = threadIdx.x;
    float S = fmaxf(g_S[b*NCLS + kc], 1e-6f);
    float invS = 1.f / S;
    for (int i = tid; i < MID; i += 256)
        ctx[i] = g_ctx[(b*NCLS + kc)*MID + i] * invS;
    __syncthreads();

    float kk = k_b[tid], vv = v_b[tid];
    const float4* kw4 = (const float4*)(k_w + tid*MID);
    const float4* vw4 = (const float4*)(v_w + tid*MID);
    for (int c4 = 0; c4 < MID/4; c4++) {
        float4 kw = kw4[c4], vw = vw4[c4];
        float c0 = ctx[c4*4], c1 = ctx[c4*4+1], c2 = ctx[c4*4+2], c3 = ctx[c4*4+3];
        kk = fmaf(c0, kw.x, fmaf(c1, kw.y, fmaf(c2, kw.z, fmaf(c3, kw.w, kk))));
        vv = fmaf(c0, vw.x, fmaf(c1, vw.y, fmaf(c2, vw.z, fmaf(c3, vw.w, vv))));
    }
    g_kmat[(b*NCLS + kc)*KCH + tid] = kk;
    g_vmat[(b*NCLS + kc)*VCH + tid] = vv;
}

// ---------------- gemm2 body (R11, proven): out[pix][n] = (Ah+Al)[pix][K] x Bw[n][K]^T ----------------
__device__ __forceinline__
void gemm2_body(const __half* __restrict__ Ahp, const __half* __restrict__ Alp,
                const __half* __restrict__ Bwp, int K, int Nst,
                float* __restrict__ outp, int mode, char* smc)
{
    uint32_t sbase = smem_u32(smc);
    int tid = threadIdx.x;
    int lane = tid & 31, warp = tid >> 5;
    int wm = warp & 3, wn = warp >> 2;
    int qrow = lane >> 2, qcol = (lane & 3) * 2;
    int n0 = blockIdx.x * 128;
    long pix0 = (long)blockIdx.y * 128;

    int arow = tid >> 1, ahalf = tid & 1;
    const __half* Abh = Ahp + (pix0 + arow) * K + ahalf * 16;
    const __half* Abl = Alp + (pix0 + arow) * K + ahalf * 16;
    const __half* Bb  = Bwp + (long)(n0 + arow) * K + ahalf * 16;
    uint32_t soff = (uint32_t)(arow * G2_STR + ahalf * 16) * 2;

    float d[2][8][4];
    #pragma unroll
    for (int mt = 0; mt < 2; mt++)
        #pragma unroll
        for (int nt = 0; nt < 8; nt++)
            #pragma unroll
            for (int e = 0; e < 4; e++) d[mt][nt][e] = 0.f;

    int nCh = K >> 5;
    {
        uint32_t st = sbase;
        cp16(st + soff,                Abh);  cp16(st + soff + 16,                Abh + 8);
        cp16(st + G2_REG*2 + soff,     Abl);  cp16(st + G2_REG*2 + soff + 16,     Abl + 8);
        cp16(st + 2*G2_REG*2 + soff,   Bb);   cp16(st + 2*G2_REG*2 + soff + 16,   Bb + 8);
        cp_commit();
    }
    for (int it = 0; it < nCh; it++) {
        int s = it & 1;
        if (it + 1 < nCh) {
            int c0 = (it + 1) * 32;
            uint32_t st = sbase + (uint32_t)(1 - s) * G2_STAGE;
            cp16(st + soff,              Abh + c0);  cp16(st + soff + 16,              Abh + c0 + 8);
            cp16(st + G2_REG*2 + soff,   Abl + c0);  cp16(st + G2_REG*2 + soff + 16,   Abl + c0 + 8);
            cp16(st + 2*G2_REG*2 + soff, Bb + c0);   cp16(st + 2*G2_REG*2 + soff + 16, Bb + c0 + 8);
            cp_commit();
            asm volatile("cp.async.wait_group 1;");
        } else {
            asm volatile("cp.async.wait_group 0;");
        }
        __syncthreads();

        const __half* sp = (const __half*)(smc + (size_t)s * G2_STAGE);
        const __half* Ah = sp;
        const __half* Al = sp + G2_REG;
        const __half* Bh = sp + 2*G2_REG;

        #pragma unroll
        for (int ks = 0; ks < 2; ks++) {
            int k0 = ks * 16 + qcol;
            uint32_t a[2][4], al[2][4], bh[8][2];
            #pragma unroll
            for (int mt = 0; mt < 2; mt++) {
                int r0 = wm * 32 + mt * 16 + qrow;
                a[mt][0] = *(const uint32_t*)(Ah + r0*G2_STR + k0);
                a[mt][1] = *(const uint32_t*)(Ah + (r0+8)*G2_STR + k0);
                a[mt][2] = *(const uint32_t*)(Ah + r0*G2_STR + k0 + 8);
                a[mt][3] = *(const uint32_t*)(Ah + (r0+8)*G2_STR + k0 + 8);
                al[mt][0] = *(const uint32_t*)(Al + r0*G2_STR + k0);
                al[mt][1] = *(const uint32_t*)(Al + (r0+8)*G2_STR + k0);
                al[mt][2] = *(const uint32_t*)(Al + r0*G2_STR + k0 + 8);
                al[mt][3] = *(const uint32_t*)(Al + (r0+8)*G2_STR + k0 + 8);
            }
            #pragma unroll
            for (int nt = 0; nt < 8; nt++) {
                int nn = wn * 64 + nt * 8 + qrow;
                bh[nt][0] = *(const uint32_t*)(Bh + nn*G2_STR + k0);
                bh[nt][1] = *(const uint32_t*)(Bh + nn*G2_STR + k0 + 8);
            }
            #pragma unroll
            for (int mt = 0; mt < 2; mt++)
                #pragma unroll
                for (int nt = 0; nt < 8; nt++) {
                    mma16816(d[mt][nt], a[mt], bh[nt]);
                    mma16816(d[mt][nt], al[mt], bh[nt]);
                }
        }
        __syncthreads();
    }

    if (mode == 0) {
        #pragma unroll
        for (int mt = 0; mt < 2; mt++) {
            long r = pix0 + wm * 32 + mt * 16 + qrow;
            #pragma unroll
            for (int nt = 0; nt < 8; nt++) {
                int ncol = n0 + wn * 64 + nt * 8 + qcol;
                float* p0 = outp + r * Nst + ncol;
                float* p1 = p0 + (long)8 * Nst;
                *(float2*)p0 = make_float2(d[mt][nt][0], d[mt][nt][1]);
                *(float2*)p1 = make_float2(d[mt][nt][2], d[mt][nt][3]);
            }
        }
    } else {
        float* es = (float*)smc;
        #pragma unroll
        for (int mt = 0; mt < 2; mt++) {
            int m = wm * 32 + mt * 16 + qrow;
            #pragma unroll
            for (int nt = 0; nt < 8; nt++) {
                int n = wn * 64 + nt * 8 + qcol;
                es[n*132 + m]       = d[mt][nt][0];
                es[(n+1)*132 + m]   = d[mt][nt][1];
                es[n*132 + m + 8]   = d[mt][nt][2];
                es[(n+1)*132 + m+8] = d[mt][nt][3];
            }
        }
        __syncthreads();
        int n = tid >> 1;
        int mh = (tid & 1) * 64;
        int b = (int)(pix0 >> 14);
        int hw0 = (int)(pix0 & (HW-1));
        float* dst = outp + ((long)(b * MID + n0 + n)) * HW + hw0 + mh;
        const float* src = es + n*132 + mh;
        #pragma unroll
        for (int j = 0; j < 16; j++) {
            float4 o = ((float4*)dst)[j];
            float4 a = ((const float4*)src)[j];
            o.x += a.x; o.y += a.y; o.z += a.z; o.w += a.w;
            ((float4*)dst)[j] = o;
        }
    }
}

// wrapper kernels: bind device-global pointers IN DEVICE CODE
__global__ void __launch_bounds__(256) gemm2_q() {
    extern __shared__ char smc[];
    gemm2_body(g_xh16, g_xl16, g_qw16, MID, KCH, g_q, 0, smc);
}
__global__ void __launch_bounds__(256) gemm2_obj() {
    extern __shared__ char smc[];
    gemm2_body(g_aggh, g_aggl, g_ow16, VCH, 0, g_x, 1, smc);
}

// ---------------- attention: reads q[pix][d], writes agg fp16 hi/lo [pix][v] ----------------
__global__ __launch_bounds__(256)
void attention_kernel() {
    __shared__ float ks[NCLS*KCH];
    __shared__ float vs[NCLS*VCH];
    int tid = threadIdx.x;
    int pix = blockIdx.x * 256 + tid;
    int b = pix >> 14;
    for (int i = tid; i < NCLS*KCH; i += 256) ks[i] = g_kmat[b*NCLS*KCH + i];
    for (int i = tid; i < NCLS*VCH; i += 256) vs[i] = g_vmat[b*NCLS*VCH + i];
    __syncthreads();

    float s[NCLS];
    #pragma unroll
    for (int k = 0; k < NCLS; k++) s[k] = 0.f;
    const float4* qp = (const float4*)(g_q + (long)pix * KCH);
    for (int d4 = 0; d4 < KCH/4; d4++) {
        float4 q4 = qp[d4];
        float qv[4] = {q4.x, q4.y, q4.z, q4.w};
        #pragma unroll
        for (int j = 0; j < 4; j++) {
            float q = qv[j];
            int d = d4*4 + j;
            #pragma unroll
            for (int k = 0; k < NCLS; k++) s[k] = fmaf(q, ks[k*KCH + d], s[k]);
        }
    }
    const float scale = 0.0625f;
    float mx = -1e30f;
    #pragma unroll
    for (int k = 0; k < NCLS; k++) { s[k] *= scale; mx = fmaxf(mx, s[k]); }
    float sum = 0.f;
    #pragma unroll
    for (int k = 0; k < NCLS; k++) { s[k] = expf(s[k] - mx); sum += s[k]; }
    float inv = 1.f / sum;
    #pragma unroll
    for (int k = 0; k < NCLS; k++) s[k] *= inv;

    long pbase = (long)pix * VCH;
    for (int v0 = 0; v0 < VCH; v0 += 8) {
        __align__(16) __half hb[8];
        __align__(16) __half lb[8];
        #pragma unroll
        for (int vv = 0; vv < 8; vv++) {
            int v = v0 + vv;
            float o = 0.f;
            #pragma unroll
            for (int k = 0; k < NCLS; k++) o = fmaf(s[k], vs[k*VCH + v], o);
            __half h = __float2half_rn(o);
            hb[vv] = h;
            lb[vv] = __float2half_rn(o - __half2float(h));
        }
        *(uint4*)&g_aggh[pbase + v0] = *(const uint4*)hb;
        *(uint4*)&g_aggl[pbase + v0] = *(const uint4*)lb;
    }
}

// ---------------- cls head ----------------
__global__ __launch_bounds__(256)
void cls_kernel(const float* __restrict__ cls_w, const float* __restrict__ cls_b,
                float* __restrict__ logits) {
    __shared__ float sw[NCLS*MID];
    __shared__ float sb[NCLS];
    int tid = threadIdx.x;
    for (int i = tid; i < NCLS*MID; i += 256) sw[i] = cls_w[i];
    if (tid < NCLS) sb[tid] = cls_b[tid];
    __syncthreads();

    int pix = blockIdx.x * 256 + tid;
    int b = pix >> 14, hw = pix & (HW-1);
    float acc[NCLS];
    #pragma unroll
    for (int k = 0; k < NCLS; k++) acc[k] = 0.f;
    const float* xb = g_x + (long)b * MID * HW + hw;
    for (int c = 0; c < MID; c++) {
        float v = xb[(long)c*HW];
        #pragma unroll
        for (int k = 0; k < NCLS; k++) acc[k] = fmaf(v, sw[k*MID + c], acc[k]);
    }
    #pragma unroll
    for (int k = 0; k < NCLS; k++)
        logits[(b*NCLS + k)*HW + hw] = acc[k] + sb[k];
}

// ---------------- launch ----------------
extern "C" void kernel_launch(void* const* d_in, const int* in_sizes, int n_in,
                              void* d_out, int out_size) {
    const float* feats = (const float*)d_in[0];
    const float* w3    = (const float*)d_in[1];
    const float* gamma = (const float*)d_in[2];
    const float* beta  = (const float*)d_in[3];
    const float* aux_w = (const float*)d_in[4];
    const float* aux_b = (const float*)d_in[5];
    const float* q_w   = (const float*)d_in[6];
    const float* k_w   = (const float*)d_in[7];
    const float* k_b   = (const float*)d_in[8];
    const float* v_w   = (const float*)d_in[9];
    const float* v_b   = (const float*)d_in[10];
    const float* out_w = (const float*)d_in[11];
    const float* cls_w = (const float*)d_in[12];
    const float* cls_b = (const float*)d_in[13];

    float* logits  = (float*)d_out;
    float* aux_out = (float*)d_out + BSZ*NCLS*HW;

    cudaFuncSetAttribute(conv_mma, cudaFuncAttributeMaxDynamicSharedMemorySize, SMEM_DYN);
    cudaFuncSetAttribute(gemm2_q,   cudaFuncAttributeMaxDynamicSharedMemorySize, G2_SMEM);
    cudaFuncSetAttribute(gemm2_obj, cudaFuncAttributeMaxDynamicSharedMemorySize, G2_SMEM);

    long n4 = (long)BSZ*PH*PW*CIN / 8;
    zero_pad<<<(int)((n4 + 255) / 256), 256>>>();
    nhwc_prep<<<BSZ*IMG_H, 256>>>(feats);
    w3_prep<<<(9*MID*CIN + 255)/256, 256>>>(w3);
    w16_prep<<<(MID*VCH + 255)/256, 256>>>(q_w, out_w);
    zero_kernel<<<(BSZ*NCLS*MID + 255)/256, 256>>>();
    conv_mma<<<dim3(MID/BN, BSZ*IMG_H), 256, SMEM_DYN>>>();
    bn_stats<<<MID, 256>>>(gamma, beta);
    bn_aux_softmax<<<BSZ*HW/256, 256>>>(aux_w, aux_b, aux_out);
    context_kernel<<<dim3(HW/512, BSZ), 512>>>();
    kv_kernel<<<BSZ*NCLS, 256>>>(k_w, k_b, v_w, v_b);
    gemm2_q<<<dim3(KCH/128, BSZ*HW/128), 256, G2_SMEM>>>();
    attention_kernel<<<BSZ*HW/256, 256>>>();
    gemm2_obj<<<dim3(MID/128, BSZ*HW/128), 256, G2_SMEM>>>();
    cls_kernel<<<BSZ*HW/256, 256>>>(cls_w, cls_b, logits);
}

// round 13
// speedup vs baseline: 2.5509x; 1.1157x over previous
#include <cuda_runtime.h>
#include <cuda_fp16.h>
#include <math.h>
#include <cstdint>

#define HW     16384
#define IMG_H  128
#define IMG_W  128
#define BSZ    4
#define CIN    720
#define MID    512
#define NCLS   19
#define KCH    256
#define VCH    256

#define PH 130
#define PW 130

// conv tiling: CTA 128(m) x 256(n), K-chunk 48, 8 warps (2m x 4n), warp tile 64x64
#define KCH_C     48
#define NCHUNKS   135
#define ASTRIDE   56
#define REG_A_ELE (128*ASTRIDE)          // 7168
#define REG_B_ELE (256*ASTRIDE)          // 14336
#define STG_ELE   (REG_A_ELE + REG_B_ELE)
#define STG_BYTES (STG_ELE*2)            // 43008
#define SMEM_DYN  (2*STG_BYTES)          // 86016 (epilogue es 67584 fits inside)

// gemm2 tiling (R11/R12 proven)
#define G2_STR    40
#define G2_REG    (128*G2_STR)
#define G2_STAGE  (3*G2_REG*2)           // 30720
#define G2_SMEM   67584

// ---------------- scratch ----------------
__device__ float g_x    [BSZ*MID*HW];
__device__ float g_q    [BSZ*HW*KCH];
__device__ float g_probs[BSZ*NCLS*HW];
__device__ float g_S    [BSZ*NCLS];
__device__ float g_ctx  [BSZ*NCLS*MID];
__device__ float g_kmat [BSZ*NCLS*KCH];
__device__ float g_vmat [BSZ*NCLS*VCH];
__device__ float g_scale[MID];
__device__ float g_shift[MID];
__device__ __align__(16) __half g_fhi[BSZ*PH*PW*CIN];
__device__ __align__(16) __half g_whi[9*MID*CIN];
__device__ __align__(16) __half g_xh16[BSZ*HW*MID];
__device__ __align__(16) __half g_xl16[BSZ*HW*MID];
__device__ __align__(16) __half g_aggh[BSZ*HW*VCH];
__device__ __align__(16) __half g_aggl[BSZ*HW*VCH];
__device__ __align__(16) __half g_qw16[KCH*MID];
__device__ __align__(16) __half g_ow16[MID*VCH];

// ---------------- helpers ----------------
__device__ __forceinline__ uint32_t smem_u32(const void* p) {
    uint32_t a;
    asm("{ .reg .u64 t; cvta.to.shared.u64 t, %1; cvt.u32.u64 %0, t; }" : "=r"(a) : "l"(p));
    return a;
}
__device__ __forceinline__ void cp16(uint32_t s, const void* g) {
    asm volatile("cp.async.cg.shared.global [%0], [%1], 16;" :: "r"(s), "l"(g));
}
__device__ __forceinline__ void cp_commit() {
    asm volatile("cp.async.commit_group;");
}
__device__ __forceinline__ void mma16816(float* d, const uint32_t* a, const uint32_t* b) {
    asm volatile(
        "mma.sync.aligned.m16n8k16.row.col.f32.f16.f16.f32 "
        "{%0,%1,%2,%3}, {%4,%5,%6,%7}, {%8,%9}, {%0,%1,%2,%3};"
        : "+f"(d[0]), "+f"(d[1]), "+f"(d[2]), "+f"(d[3])
        : "r"(a[0]), "r"(a[1]), "r"(a[2]), "r"(a[3]), "r"(b[0]), "r"(b[1]));
}

// ---------------- prep ----------------
__global__ void zero_pad() {
    long i = (long)blockIdx.x * 256 + threadIdx.x;
    const long n4 = (long)BSZ*PH*PW*CIN / 8;
    if (i < n4) ((float4*)g_fhi)[i] = make_float4(0.f, 0.f, 0.f, 0.f);
}

__global__ __launch_bounds__(256) void nhwc_prep(const float* __restrict__ feats) {
    __shared__ float tile[64][129];
    int by = blockIdx.x;
    int b = by >> 7, h = by & 127;
    int tid = threadIdx.x;
    const float* fb = feats + ((long)b * CIN) * HW + h * IMG_W;
    long obase = ((long)(b * PH + h + 1) * PW + 1) * CIN;
    for (int c0 = 0; c0 < CIN; c0 += 64) {
        int cw = CIN - c0; if (cw > 64) cw = 64;
        #pragma unroll 4
        for (int j = 0; j < 32; j++) {
            int idx = tid + j * 256;
            int c = idx >> 7, w = idx & 127;
            if (c < cw) tile[c][w] = fb[(long)(c0 + c) * HW + w];
        }
        __syncthreads();
        #pragma unroll 4
        for (int j = 0; j < 32; j++) {
            int idx = tid + j * 256;
            int w = idx >> 6, c = idx & 63;
            if (c < cw)
                g_fhi[obase + (long)w * CIN + c0 + c] = __float2half_rn(tile[c][w]);
        }
        __syncthreads();
    }
}

__global__ void w3_prep(const float* __restrict__ w3) {
    int e = blockIdx.x * 256 + threadIdx.x;
    if (e >= 9 * MID * CIN) return;
    int r = e / (MID * CIN);
    int rem = e - r * (MID * CIN);
    int o = rem / CIN;
    int c = rem - o * CIN;
    g_whi[e] = __float2half_rn(w3[(o * CIN + c) * 9 + r]);
}

__global__ void w16_prep(const float* __restrict__ qw, const float* __restrict__ ow) {
    int i = blockIdx.x * 256 + threadIdx.x;
    if (i < KCH*MID) g_qw16[i] = __float2half_rn(qw[i]);
    if (i < MID*VCH) g_ow16[i] = __float2half_rn(ow[i]);
}

__global__ void zero_kernel() {
    int i = blockIdx.x * 256 + threadIdx.x;
    if (i < BSZ*NCLS*MID) g_ctx[i] = 0.f;
    if (i < BSZ*NCLS)     g_S[i]   = 0.f;
}

// ---------------- conv3x3: CTA 128x256, warp tile 64x64, single fp16 term ----------------
__global__ __launch_bounds__(256) void conv_mma() {
    extern __shared__ __half sm[];
    uint32_t sbase = smem_u32(sm);
    int tid = threadIdx.x;
    int lane = tid & 31, warp = tid >> 5;
    int wm = warp & 1, wn = warp >> 1;           // 2m x 4n
    int qrow = lane >> 2, qcol = (lane & 3) * 2;
    int bn = blockIdx.x * 256;
    int by = blockIdx.y;
    int b = by >> 7, h = by & 127;

    const __half* fhi_b = g_fhi + (long)b * PH * PW * CIN;

    int lrow = tid >> 1, lhalf = tid & 1;        // 2 threads per row, 24 halfs each
    int thr_g = lrow * CIN + lhalf * 24;
    uint32_t thr_s = (uint32_t)(lrow * ASTRIDE + lhalf * 24) * 2;

    float d[4][8][4];
    #pragma unroll
    for (int mt = 0; mt < 4; mt++)
        #pragma unroll
        for (int nt = 0; nt < 8; nt++)
            #pragma unroll
            for (int e = 0; e < 4; e++) d[mt][nt][e] = 0.f;

    int nr = 0, nci = 0, nc0 = 0;

    // prologue: chunk 0 -> stage 0
    {
        int ab = h * PW * CIN + thr_g;
        uint32_t st = sbase;
        #pragma unroll
        for (int j = 0; j < 3; j++)
            cp16(st + thr_s + j*16, fhi_b + ab + j*8);
        #pragma unroll
        for (int g = 0; g < 2; g++) {
            int bb = (bn + g*128) * CIN + thr_g;
            uint32_t bs = REG_A_ELE*2 + (uint32_t)(g*128*ASTRIDE)*2 + thr_s;
            #pragma unroll
            for (int j = 0; j < 3; j++)
                cp16(st + bs + j*16, g_whi + bb + j*8);
        }
        cp_commit();
    }
    nci = 1; nc0 = KCH_C;

    for (int it = 0; it < NCHUNKS; it++) {
        int s = it & 1;
        if (it + 1 < NCHUNKS) {
            int ky = nr / 3, kx = nr - ky * 3;
            int ab = ((h + ky) * PW + kx) * CIN + nc0 + thr_g;
            uint32_t st = sbase + (uint32_t)(1 - s) * STG_BYTES;
            #pragma unroll
            for (int j = 0; j < 3; j++)
                cp16(st + thr_s + j*16, fhi_b + ab + j*8);
            #pragma unroll
            for (int g = 0; g < 2; g++) {
                int bb = (nr * MID + bn + g*128) * CIN + nc0 + thr_g;
                uint32_t bs = REG_A_ELE*2 + (uint32_t)(g*128*ASTRIDE)*2 + thr_s;
                #pragma unroll
                for (int j = 0; j < 3; j++)
                    cp16(st + bs + j*16, g_whi + bb + j*8);
            }
            cp_commit();
            nci++; nc0 += KCH_C;
            if (nci == 15) { nci = 0; nc0 = 0; nr++; }
            asm volatile("cp.async.wait_group 1;");
        } else {
            asm volatile("cp.async.wait_group 0;");
        }
        __syncthreads();

        const __half* st = sm + (size_t)s * STG_ELE;
        const __half* Ah = st;
        const __half* Bh = st + REG_A_ELE;

        #pragma unroll
        for (int ks = 0; ks < 3; ks++) {
            int k0 = ks * 16 + qcol;
            uint32_t ah[4][4], bh[8][2];
            #pragma unroll
            for (int mt = 0; mt < 4; mt++) {
                int r0 = wm * 64 + mt * 16 + qrow;
                ah[mt][0] = *(const uint32_t*)(Ah + r0*ASTRIDE + k0);
                ah[mt][1] = *(const uint32_t*)(Ah + (r0+8)*ASTRIDE + k0);
                ah[mt][2] = *(const uint32_t*)(Ah + r0*ASTRIDE + k0 + 8);
                ah[mt][3] = *(const uint32_t*)(Ah + (r0+8)*ASTRIDE + k0 + 8);
            }
            #pragma unroll
            for (int nt = 0; nt < 8; nt++) {
                int n0r = wn * 64 + nt * 8 + qrow;
                bh[nt][0] = *(const uint32_t*)(Bh + n0r*ASTRIDE + k0);
                bh[nt][1] = *(const uint32_t*)(Bh + n0r*ASTRIDE + k0 + 8);
            }
            #pragma unroll
            for (int mt = 0; mt < 4; mt++)
                #pragma unroll
                for (int nt = 0; nt < 8; nt++)
                    mma16816(d[mt][nt], ah[mt], bh[nt]);
        }
        __syncthreads();
    }

    // epilogue: two 128-channel halves through SMEM transpose, coalesced float4 stores
    float* es = (float*)sm;   // [128 n][132 m]
    #pragma unroll
    for (int nh = 0; nh < 2; nh++) {
        if ((wn >> 1) == nh) {
            #pragma unroll
            for (int mt = 0; mt < 4; mt++) {
                int m = wm * 64 + mt * 16 + qrow;
                #pragma unroll
                for (int nt = 0; nt < 8; nt++) {
                    int n = (wn & 1) * 64 + nt * 8 + qcol;
                    es[n*132 + m]       = d[mt][nt][0];
                    es[(n+1)*132 + m]   = d[mt][nt][1];
                    es[n*132 + m + 8]   = d[mt][nt][2];
                    es[(n+1)*132 + m+8] = d[mt][nt][3];
                }
            }
        }
        __syncthreads();
        {
            int n = tid >> 1;
            int mh = (tid & 1) * 64;
            float* dst = g_x + ((long)(b * MID + bn + nh*128 + n)) * HW + h * IMG_W + mh;
            const float* src = es + n*132 + mh;
            #pragma unroll
            for (int j = 0; j < 16; j++)
                ((float4*)dst)[j] = ((const float4*)src)[j];
        }
        __syncthreads();
    }
}

// ---------------- BN stats per channel ----------------
__global__ void bn_stats(const float* __restrict__ gamma, const float* __restrict__ beta) {
    int c = blockIdx.x, tid = threadIdx.x;
    float s = 0.f, sq = 0.f;
    for (int b = 0; b < BSZ; b++) {
        const float* p = g_x + (b*MID + c)*HW;
        for (int i = tid; i < HW; i += 256) { float v = p[i]; s += v; sq += v*v; }
    }
    __shared__ float ss[256], s2[256];
    ss[tid] = s; s2[tid] = sq; __syncthreads();
    for (int st = 128; st > 0; st >>= 1) {
        if (tid < st) { ss[tid] += ss[tid+st]; s2[tid] += s2[tid+st]; }
        __syncthreads();
    }
    if (tid == 0) {
        float n    = (float)(BSZ*HW);
        float mean = ss[0] / n;
        float var  = s2[0] / n - mean*mean;
        float rstd = rsqrtf(var + 1e-5f);
        float sc   = gamma[c] * rstd;
        g_scale[c] = sc;
        g_shift[c] = beta[c] - mean * sc;
    }
}

// ---------------- fused: BN apply + relu + fp16 split emit [pix][c] + aux + softmax ----------------
__global__ __launch_bounds__(256)
void bn_aux_softmax(const float* __restrict__ aux_w, const float* __restrict__ aux_b,
                    float* __restrict__ aux_out) {
    __shared__ float sw[NCLS*MID];
    __shared__ float ssc[MID], ssh[MID];
    __shared__ float sb[NCLS], sS[NCLS];
    int tid = threadIdx.x;
    for (int i = tid; i < NCLS*MID; i += 256) sw[i] = aux_w[i];
    for (int i = tid; i < MID; i += 256) { ssc[i] = g_scale[i]; ssh[i] = g_shift[i]; }
    if (tid < NCLS) { sb[tid] = aux_b[tid]; sS[tid] = 0.f; }
    __syncthreads();

    int pix = blockIdx.x * 256 + tid;
    int b   = pix >> 14;
    int hw  = pix & (HW-1);
    float acc[NCLS];
    #pragma unroll
    for (int k = 0; k < NCLS; k++) acc[k] = 0.f;

    float* xb = g_x + (long)b * MID * HW + hw;
    long pbase = (long)pix * MID;
    for (int c0 = 0; c0 < MID; c0 += 8) {
        __align__(16) __half hb[8];
        __align__(16) __half lb[8];
        #pragma unroll
        for (int cc = 0; cc < 8; cc++) {
            int c = c0 + cc;
            float v = xb[(long)c*HW];
            v = fmaf(v, ssc[c], ssh[c]);
            v = fmaxf(v, 0.f);
            xb[(long)c*HW] = v;
            __half hv = __float2half_rn(v);
            hb[cc] = hv;
            lb[cc] = __float2half_rn(v - __half2float(hv));
            #pragma unroll
            for (int k = 0; k < NCLS; k++) acc[k] = fmaf(v, sw[k*MID + c], acc[k]);
        }
        *(uint4*)&g_xh16[pbase + c0] = *(const uint4*)hb;
        *(uint4*)&g_xl16[pbase + c0] = *(const uint4*)lb;
    }
    float mx = -1e30f;
    #pragma unroll
    for (int k = 0; k < NCLS; k++) {
        acc[k] += sb[k];
        aux_out[(b*NCLS + k)*HW + hw] = acc[k];
        mx = fmaxf(mx, acc[k]);
    }
    float sum = 0.f;
    #pragma unroll
    for (int k = 0; k < NCLS; k++) { acc[k] = expf(acc[k] - mx); sum += acc[k]; }
    float inv = 1.f / sum;
    #pragma unroll
    for (int k = 0; k < NCLS; k++) {
        float p = acc[k] * inv;
        g_probs[(b*NCLS + k)*HW + hw] = p;
        atomicAdd(&sS[k], p);
    }
    __syncthreads();
    if (tid < NCLS) atomicAdd(&g_S[b*NCLS + tid], sS[tid]);
}

// ---------------- context ----------------
__global__ __launch_bounds__(512)
void context_kernel() {
    __shared__ float pw[NCLS][512];
    int b   = blockIdx.y;
    int n0  = blockIdx.x * 512;
    int tid = threadIdx.x;
    for (int k = 0; k < NCLS; k++)
        pw[k][tid] = g_probs[(b*NCLS + k)*HW + n0 + tid];
    __syncthreads();

    float acc[NCLS];
    #pragma unroll
    for (int k = 0; k < NCLS; k++) acc[k] = 0.f;
    const float* xr = g_x + (b*MID + tid)*HW + n0;
    for (int n = 0; n < 512; n += 4) {
        float4 xv = *(const float4*)(xr + n);
        float vv[4] = {xv.x, xv.y, xv.z, xv.w};
        #pragma unroll
        for (int dn = 0; dn < 4; dn++) {
            float v = vv[dn];
            #pragma unroll
            for (int k = 0; k < NCLS; k++) acc[k] = fmaf(v, pw[k][n + dn], acc[k]);
        }
    }
    #pragma unroll
    for (int k = 0; k < NCLS; k++)
        atomicAdd(&g_ctx[(b*NCLS + k)*MID + tid], acc[k]);
}

// ---------------- k,v from normalized context ----------------
__global__ __launch_bounds__(256)
void kv_kernel(const float* __restrict__ k_w, const float* __restrict__ k_b,
               const float* __restrict__ v_w, const float* __restrict__ v_b) {
    int b  = blockIdx.x / NCLS;
    int kc = blockIdx.x % NCLS;
    __shared__ float ctx[MID];
    int tid = threadIdx.x;
    float S = fmaxf(g_S[b*NCLS + kc], 1e-6f);
    float invS = 1.f / S;
    for (int i = tid; i < MID; i += 256)
        ctx[i] = g_ctx[(b*NCLS + kc)*MID + i] * invS;
    __syncthreads();

    float kk = k_b[tid], vv = v_b[tid];
    const float4* kw4 = (const float4*)(k_w + tid*MID);
    const float4* vw4 = (const float4*)(v_w + tid*MID);
    for (int c4 = 0; c4 < MID/4; c4++) {
        float4 kw = kw4[c4], vw = vw4[c4];
        float c0 = ctx[c4*4], c1 = ctx[c4*4+1], c2 = ctx[c4*4+2], c3 = ctx[c4*4+3];
        kk = fmaf(c0, kw.x, fmaf(c1, kw.y, fmaf(c2, kw.z, fmaf(c3, kw.w, kk))));
        vv = fmaf(c0, vw.x, fmaf(c1, vw.y, fmaf(c2, vw.z, fmaf(c3, vw.w, vv))));
    }
    g_kmat[(b*NCLS + kc)*KCH + tid] = kk;
    g_vmat[(b*NCLS + kc)*VCH + tid] = vv;
}

// ---------------- gemm2 body (R11/R12 proven) ----------------
__device__ __forceinline__
void gemm2_body(const __half* __restrict__ Ahp, const __half* __restrict__ Alp,
                const __half* __restrict__ Bwp, int K, int Nst,
                float* __restrict__ outp, int mode, char* smc)
{
    uint32_t sbase = smem_u32(smc);
    int tid = threadIdx.x;
    int lane = tid & 31, warp = tid >> 5;
    int wm = warp & 3, wn = warp >> 2;
    int qrow = lane >> 2, qcol = (lane & 3) * 2;
    int n0 = blockIdx.x * 128;
    long pix0 = (long)blockIdx.y * 128;

    int arow = tid >> 1, ahalf = tid & 1;
    const __half* Abh = Ahp + (pix0 + arow) * K + ahalf * 16;
    const __half* Abl = Alp + (pix0 + arow) * K + ahalf * 16;
    const __half* Bb  = Bwp + (long)(n0 + arow) * K + ahalf * 16;
    uint32_t soff = (uint32_t)(arow * G2_STR + ahalf * 16) * 2;

    float d[2][8][4];
    #pragma unroll
    for (int mt = 0; mt < 2; mt++)
        #pragma unroll
        for (int nt = 0; nt < 8; nt++)
            #pragma unroll
            for (int e = 0; e < 4; e++) d[mt][nt][e] = 0.f;

    int nCh = K >> 5;
    {
        uint32_t st = sbase;
        cp16(st + soff,                Abh);  cp16(st + soff + 16,                Abh + 8);
        cp16(st + G2_REG*2 + soff,     Abl);  cp16(st + G2_REG*2 + soff + 16,     Abl + 8);
        cp16(st + 2*G2_REG*2 + soff,   Bb);   cp16(st + 2*G2_REG*2 + soff + 16,   Bb + 8);
        cp_commit();
    }
    for (int it = 0; it < nCh; it++) {
        int s = it & 1;
        if (it + 1 < nCh) {
            int c0 = (it + 1) * 32;
            uint32_t st = sbase + (uint32_t)(1 - s) * G2_STAGE;
            cp16(st + soff,              Abh + c0);  cp16(st + soff + 16,              Abh + c0 + 8);
            cp16(st + G2_REG*2 + soff,   Abl + c0);  cp16(st + G2_REG*2 + soff + 16,   Abl + c0 + 8);
            cp16(st + 2*G2_REG*2 + soff, Bb + c0);   cp16(st + 2*G2_REG*2 + soff + 16, Bb + c0 + 8);
            cp_commit();
            asm volatile("cp.async.wait_group 1;");
        } else {
            asm volatile("cp.async.wait_group 0;");
        }
        __syncthreads();

        const __half* sp = (const __half*)(smc + (size_t)s * G2_STAGE);
        const __half* Ah = sp;
        const __half* Al = sp + G2_REG;
        const __half* Bh = sp + 2*G2_REG;

        #pragma unroll
        for (int ks = 0; ks < 2; ks++) {
            int k0 = ks * 16 + qcol;
            uint32_t a[2][4], al[2][4], bh[8][2];
            #pragma unroll
            for (int mt = 0; mt < 2; mt++) {
                int r0 = wm * 32 + mt * 16 + qrow;
                a[mt][0] = *(const uint32_t*)(Ah + r0*G2_STR + k0);
                a[mt][1] = *(const uint32_t*)(Ah + (r0+8)*G2_STR + k0);
                a[mt][2] = *(const uint32_t*)(Ah + r0*G2_STR + k0 + 8);
                a[mt][3] = *(const uint32_t*)(Ah + (r0+8)*G2_STR + k0 + 8);
                al[mt][0] = *(const uint32_t*)(Al + r0*G2_STR + k0);
                al[mt][1] = *(const uint32_t*)(Al + (r0+8)*G2_STR + k0);
                al[mt][2] = *(const uint32_t*)(Al + r0*G2_STR + k0 + 8);
                al[mt][3] = *(const uint32_t*)(Al + (r0+8)*G2_STR + k0 + 8);
            }
            #pragma unroll
            for (int nt = 0; nt < 8; nt++) {
                int nn = wn * 64 + nt * 8 + qrow;
                bh[nt][0] = *(const uint32_t*)(Bh + nn*G2_STR + k0);
                bh[nt][1] = *(const uint32_t*)(Bh + nn*G2_STR + k0 + 8);
            }
            #pragma unroll
            for (int mt = 0; mt < 2; mt++)
                #pragma unroll
                for (int nt = 0; nt < 8; nt++) {
                    mma16816(d[mt][nt], a[mt], bh[nt]);
                    mma16816(d[mt][nt], al[mt], bh[nt]);
                }
        }
        __syncthreads();
    }

    if (mode == 0) {
        #pragma unroll
        for (int mt = 0; mt < 2; mt++) {
            long r = pix0 + wm * 32 + mt * 16 + qrow;
            #pragma unroll
            for (int nt = 0; nt < 8; nt++) {
                int ncol = n0 + wn * 64 + nt * 8 + qcol;
                float* p0 = outp + r * Nst + ncol;
                float* p1 = p0 + (long)8 * Nst;
                *(float2*)p0 = make_float2(d[mt][nt][0], d[mt][nt][1]);
                *(float2*)p1 = make_float2(d[mt][nt][2], d[mt][nt][3]);
            }
        }
    } else {
        float* es = (float*)smc;
        #pragma unroll
        for (int mt = 0; mt < 2; mt++) {
            int m = wm * 32 + mt * 16 + qrow;
            #pragma unroll
            for (int nt = 0; nt < 8; nt++) {
                int n = wn * 64 + nt * 8 + qcol;
                es[n*132 + m]       = d[mt][nt][0];
                es[(n+1)*132 + m]   = d[mt][nt][1];
                es[n*132 + m + 8]   = d[mt][nt][2];
                es[(n+1)*132 + m+8] = d[mt][nt][3];
            }
        }
        __syncthreads();
        int n = tid >> 1;
        int mh = (tid & 1) * 64;
        int b = (int)(pix0 >> 14);
        int hw0 = (int)(pix0 & (HW-1));
        float* dst = outp + ((long)(b * MID + n0 + n)) * HW + hw0 + mh;
        const float* src = es + n*132 + mh;
        #pragma unroll
        for (int j = 0; j < 16; j++) {
            float4 o = ((float4*)dst)[j];
            float4 a = ((const float4*)src)[j];
            o.x += a.x; o.y += a.y; o.z += a.z; o.w += a.w;
            ((float4*)dst)[j] = o;
        }
    }
}

__global__ void __launch_bounds__(256) gemm2_q() {
    extern __shared__ char smc[];
    gemm2_body(g_xh16, g_xl16, g_qw16, MID, KCH, g_q, 0, smc);
}
__global__ void __launch_bounds__(256) gemm2_obj() {
    extern __shared__ char smc[];
    gemm2_body(g_aggh, g_aggl, g_ow16, VCH, 0, g_x, 1, smc);
}

// ---------------- attention ----------------
__global__ __launch_bounds__(256)
void attention_kernel() {
    __shared__ float ks[NCLS*KCH];
    __shared__ float vs[NCLS*VCH];
    int tid = threadIdx.x;
    int pix = blockIdx.x * 256 + tid;
    int b = pix >> 14;
    for (int i = tid; i < NCLS*KCH; i += 256) ks[i] = g_kmat[b*NCLS*KCH + i];
    for (int i = tid; i < NCLS*VCH; i += 256) vs[i] = g_vmat[b*NCLS*VCH + i];
    __syncthreads();

    float s[NCLS];
    #pragma unroll
    for (int k = 0; k < NCLS; k++) s[k] = 0.f;
    const float4* qp = (const float4*)(g_q + (long)pix * KCH);
    for (int d4 = 0; d4 < KCH/4; d4++) {
        float4 q4 = qp[d4];
        float qv[4] = {q4.x, q4.y, q4.z, q4.w};
        #pragma unroll
        for (int j = 0; j < 4; j++) {
            float q = qv[j];
            int d = d4*4 + j;
            #pragma unroll
            for (int k = 0; k < NCLS; k++) s[k] = fmaf(q, ks[k*KCH + d], s[k]);
        }
    }
    const float scale = 0.0625f;
    float mx = -1e30f;
    #pragma unroll
    for (int k = 0; k < NCLS; k++) { s[k] *= scale; mx = fmaxf(mx, s[k]); }
    float sum = 0.f;
    #pragma unroll
    for (int k = 0; k < NCLS; k++) { s[k] = expf(s[k] - mx); sum += s[k]; }
    float inv = 1.f / sum;
    #pragma unroll
    for (int k = 0; k < NCLS; k++) s[k] *= inv;

    long pbase = (long)pix * VCH;
    for (int v0 = 0; v0 < VCH; v0 += 8) {
        __align__(16) __half hb[8];
        __align__(16) __half lb[8];
        #pragma unroll
        for (int vv = 0; vv < 8; vv++) {
            int v = v0 + vv;
            float o = 0.f;
            #pragma unroll
            for (int k = 0; k < NCLS; k++) o = fmaf(s[k], vs[k*VCH + v], o);
            __half h = __float2half_rn(o);
            hb[vv] = h;
            lb[vv] = __float2half_rn(o - __half2float(h));
        }
        *(uint4*)&g_aggh[pbase + v0] = *(const uint4*)hb;
        *(uint4*)&g_aggl[pbase + v0] = *(const uint4*)lb;
    }
}

// ---------------- cls head ----------------
__global__ __launch_bounds__(256)
void cls_kernel(const float* __restrict__ cls_w, const float* __restrict__ cls_b,
                float* __restrict__ logits) {
    __shared__ float sw[NCLS*MID];
    __shared__ float sb[NCLS];
    int tid = threadIdx.x;
    for (int i = tid; i < NCLS*MID; i += 256) sw[i] = cls_w[i];
    if (tid < NCLS) sb[tid] = cls_b[tid];
    __syncthreads();

    int pix = blockIdx.x * 256 + tid;
    int b = pix >> 14, hw = pix & (HW-1);
    float acc[NCLS];
    #pragma unroll
    for (int k = 0; k < NCLS; k++) acc[k] = 0.f;
    const float* xb = g_x + (long)b * MID * HW + hw;
    for (int c = 0; c < MID; c++) {
        float v = xb[(long)c*HW];
        #pragma unroll
        for (int k = 0; k < NCLS; k++) acc[k] = fmaf(v, sw[k*MID + c], acc[k]);
    }
    #pragma unroll
    for (int k = 0; k < NCLS; k++)
        logits[(b*NCLS + k)*HW + hw] = acc[k] + sb[k];
}

// ---------------- launch ----------------
extern "C" void kernel_launch(void* const* d_in, const int* in_sizes, int n_in,
                              void* d_out, int out_size) {
    const float* feats = (const float*)d_in[0];
    const float* w3    = (const float*)d_in[1];
    const float* gamma = (const float*)d_in[2];
    const float* beta  = (const float*)d_in[3];
    const float* aux_w = (const float*)d_in[4];
    const float* aux_b = (const float*)d_in[5];
    const float* q_w   = (const float*)d_in[6];
    const float* k_w   = (const float*)d_in[7];
    const float* k_b   = (const float*)d_in[8];
    const float* v_w   = (const float*)d_in[9];
    const float* v_b   = (const float*)d_in[10];
    const float* out_w = (const float*)d_in[11];
    const float* cls_w = (const float*)d_in[12];
    const float* cls_b = (const float*)d_in[13];

    float* logits  = (float*)d_out;
    float* aux_out = (float*)d_out + BSZ*NCLS*HW;

    cudaFuncSetAttribute(conv_mma, cudaFuncAttributeMaxDynamicSharedMemorySize, SMEM_DYN);
    cudaFuncSetAttribute(gemm2_q,   cudaFuncAttributeMaxDynamicSharedMemorySize, G2_SMEM);
    cudaFuncSetAttribute(gemm2_obj, cudaFuncAttributeMaxDynamicSharedMemorySize, G2_SMEM);

    long n4 = (long)BSZ*PH*PW*CIN / 8;
    zero_pad<<<(int)((n4 + 255) / 256), 256>>>();
    nhwc_prep<<<BSZ*IMG_H, 256>>>(feats);
    w3_prep<<<(9*MID*CIN + 255)/256, 256>>>(w3);
    w16_prep<<<(MID*VCH + 255)/256, 256>>>(q_w, out_w);
    zero_kernel<<<(BSZ*NCLS*MID + 255)/256, 256>>>();
    conv_mma<<<dim3(MID/256, BSZ*IMG_H), 256, SMEM_DYN>>>();
    bn_stats<<<MID, 256>>>(gamma, beta);
    bn_aux_softmax<<<BSZ*HW/256, 256>>>(aux_w, aux_b, aux_out);
    context_kernel<<<dim3(HW/512, BSZ), 512>>>();
    kv_kernel<<<BSZ*NCLS, 256>>>(k_w, k_b, v_w, v_b);
    gemm2_q<<<dim3(KCH/128, BSZ*HW/128), 256, G2_SMEM>>>();
    attention_kernel<<<BSZ*HW/256, 256>>>();
    gemm2_obj<<<dim3(MID/128, BSZ*HW/128), 256, G2_SMEM>>>();
    cls_kernel<<<BSZ*HW/256, 256>>>(cls_w, cls_b, logits);
}